// round 10
// baseline (speedup 1.0000x reference)
#include <cuda_runtime.h>
#include <math.h>

#define TT 1024
#define SS 1024
#define BB 8
#define EE 768
#define HH 12
#define DD 64
#define MM (TT*BB)
#define BE (BB*EE)

#define PAD 20          // smem row stride (floats) for 16-wide k tiles -> conflict-free frags
#define PADV 68         // smem row stride for V tiles [16][64]

// ---------------- scratch ----------------
static __device__ float g_q[(size_t)TT * BB * EE];
static __device__ float g_k[(size_t)SS * BB * EE];
static __device__ float g_v[(size_t)SS * BB * EE];
static __device__ float g_w[(size_t)BB * HH * TT * SS];   // logits -> softmax weights
static __device__ float g_attn[(size_t)TT * BB * EE];
static __device__ float g_partBT[BB * TT];                // per (b,t) bce partials

// ---------------- helpers ----------------
__device__ __forceinline__ unsigned f2tf32(float f) {
    unsigned u;
    asm("cvt.rna.tf32.f32 %0, %1;" : "=r"(u) : "f"(f));
    return u;
}

__device__ __forceinline__ void mma_tf32(float c[4],
                                         unsigned a0, unsigned a1, unsigned a2, unsigned a3,
                                         unsigned b0, unsigned b1) {
    asm volatile("mma.sync.aligned.m16n8k8.row.col.f32.tf32.tf32.f32 "
                 "{%0,%1,%2,%3}, {%4,%5,%6,%7}, {%8,%9}, {%0,%1,%2,%3};"
                 : "+f"(c[0]), "+f"(c[1]), "+f"(c[2]), "+f"(c[3])
                 : "r"(a0), "r"(a1), "r"(a2), "r"(a3), "r"(b0), "r"(b1));
}

__device__ __forceinline__ void cvt_store4(unsigned* p, float4 v) {
    uint4 u;
    u.x = f2tf32(v.x); u.y = f2tf32(v.y); u.z = f2tf32(v.z); u.w = f2tf32(v.w);
    *(uint4*)p = u;
}

// ============================================================================
// SGEMM (tf32 mma): C[M,N] = (A[M,K] @ W[N,K]^T + bias) * alpha
// block tile 128x128, BK=16, 8 warps (4x2), warp tile 32x64
// ============================================================================
__global__ __launch_bounds__(256)
void sgemm_nt_mma(const float* __restrict__ A, const float* __restrict__ W,
                  const float* __restrict__ bias, float* __restrict__ C,
                  int M, int N, int K, float alpha)
{
    __shared__ unsigned As[128 * PAD];
    __shared__ unsigned Ws[128 * PAD];

    const int bm = blockIdx.y * 128;
    const int bn = blockIdx.x * 128;
    const int tid  = threadIdx.x;
    const int wid  = tid >> 5;
    const int lane = tid & 31;
    const int wm = (wid >> 1) * 32;
    const int wn = (wid & 1) * 64;
    const int grp = lane >> 2;
    const int tig = lane & 3;

    float acc[2][8][4] = {};
    float4 ra[2], rw[2];

    const int r0 = tid >> 2,        q0 = (tid & 3) * 4;
    const int r1 = (tid + 256) >> 2, q1 = q0;   // second half rows 64..127

    // prefetch k0 = 0
    ra[0] = *(const float4*)(A + (size_t)(bm + r0) * K + q0);
    ra[1] = *(const float4*)(A + (size_t)(bm + r1) * K + q1);
    rw[0] = *(const float4*)(W + (size_t)(bn + r0) * K + q0);
    rw[1] = *(const float4*)(W + (size_t)(bn + r1) * K + q1);

    for (int k0 = 0; k0 < K; k0 += 16) {
        cvt_store4(As + r0 * PAD + q0, ra[0]);
        cvt_store4(As + r1 * PAD + q1, ra[1]);
        cvt_store4(Ws + r0 * PAD + q0, rw[0]);
        cvt_store4(Ws + r1 * PAD + q1, rw[1]);
        __syncthreads();

        if (k0 + 16 < K) {
            int kn = k0 + 16;
            ra[0] = *(const float4*)(A + (size_t)(bm + r0) * K + kn + q0);
            ra[1] = *(const float4*)(A + (size_t)(bm + r1) * K + kn + q1);
            rw[0] = *(const float4*)(W + (size_t)(bn + r0) * K + kn + q0);
            rw[1] = *(const float4*)(W + (size_t)(bn + r1) * K + kn + q1);
        }

        #pragma unroll
        for (int ks = 0; ks < 2; ks++) {
            unsigned a[2][4], b[8][2];
            #pragma unroll
            for (int mi = 0; mi < 2; mi++) {
                const unsigned* p = As + (wm + mi * 16 + grp) * PAD + ks * 8 + tig;
                a[mi][0] = p[0];
                a[mi][1] = p[8 * PAD];
                a[mi][2] = p[4];
                a[mi][3] = p[8 * PAD + 4];
            }
            #pragma unroll
            for (int ni = 0; ni < 8; ni++) {
                const unsigned* p = Ws + (wn + ni * 8 + grp) * PAD + ks * 8 + tig;
                b[ni][0] = p[0];
                b[ni][1] = p[4];
            }
            #pragma unroll
            for (int mi = 0; mi < 2; mi++)
                #pragma unroll
                for (int ni = 0; ni < 8; ni++)
                    mma_tf32(acc[mi][ni], a[mi][0], a[mi][1], a[mi][2], a[mi][3],
                             b[ni][0], b[ni][1]);
        }
        __syncthreads();
    }

    #pragma unroll
    for (int mi = 0; mi < 2; mi++) {
        int row = bm + wm + mi * 16 + grp;
        #pragma unroll
        for (int ni = 0; ni < 8; ni++) {
            int col = bn + wn + ni * 8 + 2 * tig;
            float bv0 = bias[col], bv1 = bias[col + 1];
            float2 v0 = { (acc[mi][ni][0] + bv0) * alpha, (acc[mi][ni][1] + bv1) * alpha };
            float2 v1 = { (acc[mi][ni][2] + bv0) * alpha, (acc[mi][ni][3] + bv1) * alpha };
            *(float2*)(C + (size_t)row * N + col)       = v0;
            *(float2*)(C + (size_t)(row + 8) * N + col) = v1;
        }
    }
}

// ============================================================================
// logits (tf32 mma): g_w[b,h,t,s] = Q.K^T + attn_mask, -inf on padding
// block 128(t) x 128(s), K=D=64 in 4 x BK16 tiles, per (b,h) in z
// ============================================================================
__global__ __launch_bounds__(256)
void logits_mma(const float* __restrict__ attn_mask,
                const unsigned char* __restrict__ pad_mask)
{
    __shared__ unsigned Qs[128 * PAD];
    __shared__ unsigned Ks[128 * PAD];

    const int bh = blockIdx.z;
    const int b  = bh / HH;
    const int h  = bh % HH;
    const int t0 = blockIdx.y * 128;
    const int s0 = blockIdx.x * 128;

    const int tid  = threadIdx.x;
    const int wid  = tid >> 5;
    const int lane = tid & 31;
    const int wm = (wid >> 1) * 32;
    const int wn = (wid & 1) * 64;
    const int grp = lane >> 2;
    const int tig = lane & 3;

    const float* qb = g_q + (size_t)b * EE + h * DD;
    const float* kb = g_k + (size_t)b * EE + h * DD;

    float acc[2][8][4] = {};
    float4 ra[2], rw[2];

    const int r0 = tid >> 2,         q0 = (tid & 3) * 4;
    const int r1 = (tid + 256) >> 2;

    ra[0] = *(const float4*)(qb + (size_t)(t0 + r0) * BE + q0);
    ra[1] = *(const float4*)(qb + (size_t)(t0 + r1) * BE + q0);
    rw[0] = *(const float4*)(kb + (size_t)(s0 + r0) * BE + q0);
    rw[1] = *(const float4*)(kb + (size_t)(s0 + r1) * BE + q0);

    for (int k0 = 0; k0 < DD; k0 += 16) {
        cvt_store4(Qs + r0 * PAD + q0, ra[0]);
        cvt_store4(Qs + r1 * PAD + q0, ra[1]);
        cvt_store4(Ks + r0 * PAD + q0, rw[0]);
        cvt_store4(Ks + r1 * PAD + q0, rw[1]);
        __syncthreads();

        if (k0 + 16 < DD) {
            int kn = k0 + 16;
            ra[0] = *(const float4*)(qb + (size_t)(t0 + r0) * BE + kn + q0);
            ra[1] = *(const float4*)(qb + (size_t)(t0 + r1) * BE + kn + q0);
            rw[0] = *(const float4*)(kb + (size_t)(s0 + r0) * BE + kn + q0);
            rw[1] = *(const float4*)(kb + (size_t)(s0 + r1) * BE + kn + q0);
        }

        #pragma unroll
        for (int ks = 0; ks < 2; ks++) {
            unsigned a[2][4], bfr[8][2];
            #pragma unroll
            for (int mi = 0; mi < 2; mi++) {
                const unsigned* p = Qs + (wm + mi * 16 + grp) * PAD + ks * 8 + tig;
                a[mi][0] = p[0]; a[mi][1] = p[8 * PAD]; a[mi][2] = p[4]; a[mi][3] = p[8 * PAD + 4];
            }
            #pragma unroll
            for (int ni = 0; ni < 8; ni++) {
                const unsigned* p = Ks + (wn + ni * 8 + grp) * PAD + ks * 8 + tig;
                bfr[ni][0] = p[0]; bfr[ni][1] = p[4];
            }
            #pragma unroll
            for (int mi = 0; mi < 2; mi++)
                #pragma unroll
                for (int ni = 0; ni < 8; ni++)
                    mma_tf32(acc[mi][ni], a[mi][0], a[mi][1], a[mi][2], a[mi][3],
                             bfr[ni][0], bfr[ni][1]);
        }
        __syncthreads();
    }

    const float NEG = __int_as_float(0xff800000);
    float* out = g_w + (size_t)bh * TT * SS;

    #pragma unroll
    for (int mi = 0; mi < 2; mi++) {
        int t = t0 + wm + mi * 16 + grp;
        #pragma unroll
        for (int ni = 0; ni < 8; ni++) {
            int s = s0 + wn + ni * 8 + 2 * tig;
            bool p0 = pad_mask[b * SS + s];
            bool p1 = pad_mask[b * SS + s + 1];
            float2 v0, v1;
            v0.x = p0 ? NEG : acc[mi][ni][0] + attn_mask[(size_t)t * SS + s];
            v0.y = p1 ? NEG : acc[mi][ni][1] + attn_mask[(size_t)t * SS + s + 1];
            v1.x = p0 ? NEG : acc[mi][ni][2] + attn_mask[(size_t)(t + 8) * SS + s];
            v1.y = p1 ? NEG : acc[mi][ni][3] + attn_mask[(size_t)(t + 8) * SS + s + 1];
            *(float2*)(out + (size_t)t * SS + s)       = v0;
            *(float2*)(out + (size_t)(t + 8) * SS + s) = v1;
        }
    }
}

// ============================================================================
// Fused softmax (in-place on g_w, per head) + head-max + BCE per (b,t)
// ============================================================================
__global__ __launch_bounds__(256)
void smax_arc_kernel(const int* __restrict__ target_rel)
{
    const int t = blockIdx.x;
    const int b = blockIdx.y;
    const int tid  = threadIdx.x;
    const int lane = tid & 31;
    const int wid  = tid >> 5;
    __shared__ float red[40];

    float hm0 = 0.f, hm1 = 0.f, hm2 = 0.f, hm3 = 0.f;

    for (int h = 0; h < HH; h++) {
        float* row = g_w + (((size_t)(b * HH + h)) * TT + t) * SS;
        float4 v = ((float4*)row)[tid];

        float m = fmaxf(fmaxf(v.x, v.y), fmaxf(v.z, v.w));
        #pragma unroll
        for (int o = 16; o > 0; o >>= 1) m = fmaxf(m, __shfl_xor_sync(~0u, m, o));
        if (lane == 0) red[wid] = m;
        __syncthreads();
        if (wid == 0) {
            float mm = red[lane & 7];
            #pragma unroll
            for (int o = 4; o > 0; o >>= 1) mm = fmaxf(mm, __shfl_xor_sync(~0u, mm, o));
            if (lane == 0) red[32] = mm;
        }
        __syncthreads();
        m = red[32];

        v.x = __expf(v.x - m); v.y = __expf(v.y - m);
        v.z = __expf(v.z - m); v.w = __expf(v.w - m);
        float s = v.x + v.y + v.z + v.w;
        #pragma unroll
        for (int o = 16; o > 0; o >>= 1) s += __shfl_xor_sync(~0u, s, o);
        if (lane == 0) red[wid + 8] = s;
        __syncthreads();
        if (wid == 0) {
            float ss = red[8 + (lane & 7)];
            #pragma unroll
            for (int o = 4; o > 0; o >>= 1) ss += __shfl_xor_sync(~0u, ss, o);
            if (lane == 0) red[33] = ss;
        }
        __syncthreads();
        float inv = 1.f / red[33];

        v.x *= inv; v.y *= inv; v.z *= inv; v.w *= inv;
        ((float4*)row)[tid] = v;
        hm0 = fmaxf(hm0, v.x); hm1 = fmaxf(hm1, v.y);
        hm2 = fmaxf(hm2, v.z); hm3 = fmaxf(hm3, v.w);
        __syncthreads();
    }

    // BCE: rel==0 -> 0; rel==1 -> -max(log(w),-100); rel==2 -> -max(log1p(-w),-100)
    int4 rel = ((const int4*)(target_rel + ((size_t)t * BB + b) * SS))[tid];
    float sum = 0.f;
    if (rel.x == 1) sum -= fmaxf(logf(hm0), -100.f); else if (rel.x == 2) sum -= fmaxf(log1pf(-hm0), -100.f);
    if (rel.y == 1) sum -= fmaxf(logf(hm1), -100.f); else if (rel.y == 2) sum -= fmaxf(log1pf(-hm1), -100.f);
    if (rel.z == 1) sum -= fmaxf(logf(hm2), -100.f); else if (rel.z == 2) sum -= fmaxf(log1pf(-hm2), -100.f);
    if (rel.w == 1) sum -= fmaxf(logf(hm3), -100.f); else if (rel.w == 2) sum -= fmaxf(log1pf(-hm3), -100.f);

    #pragma unroll
    for (int o = 16; o > 0; o >>= 1) sum += __shfl_xor_sync(~0u, sum, o);
    if (lane == 0) red[wid + 16] = sum;
    __syncthreads();
    if (wid == 0) {
        float ss = red[16 + (lane & 7)];
        #pragma unroll
        for (int o = 4; o > 0; o >>= 1) ss += __shfl_xor_sync(~0u, ss, o);
        if (lane == 0) g_partBT[b * TT + t] = ss;
    }
}

__global__ void finalize_kernel(const float* __restrict__ strategy_id,
                                float* __restrict__ out)
{
    __shared__ float red[256];
    int b = blockIdx.x;
    int tid = threadIdx.x;
    float s = 0.f;
    for (int i = tid; i < TT; i += 256) s += g_partBT[b * TT + i];
    red[tid] = s; __syncthreads();
    #pragma unroll
    for (int o = 128; o > 0; o >>= 1) {
        if (tid < o) red[tid] += red[tid + o];
        __syncthreads();
    }
    if (tid == 0) out[b] = red[0] * strategy_id[b];
}

// ============================================================================
// attn·V (tf32 mma): g_attn[t,b,h*64+d] = sum_s w[b,h,t,s] * v[s,b,h,d]
// block 128(t) x 64(d), K=S=1024 in BK16 tiles, per (b,h) in y
// warp tile 32x32 (8 warps, 4x2)
// ============================================================================
__global__ __launch_bounds__(256)
void attnv_mma()
{
    __shared__ unsigned Asm[128 * PAD];   // weights [t][k]
    __shared__ unsigned Vsm[16 * PADV];   // V tile [k(s)][n(d)]

    const int bh = blockIdx.y;
    const int b  = bh / HH;
    const int h  = bh % HH;
    const int t0 = blockIdx.x * 128;

    const int tid  = threadIdx.x;
    const int wid  = tid >> 5;
    const int lane = tid & 31;
    const int wm = (wid >> 1) * 32;
    const int wn = (wid & 1) * 32;
    const int grp = lane >> 2;
    const int tig = lane & 3;

    const float* wb = g_w + ((size_t)bh * TT + t0) * SS;
    const float* vb = g_v + (size_t)b * EE + h * DD;

    float acc[2][4][4] = {};
    float4 ra[2], rv;

    const int r0 = tid >> 2,         q0 = (tid & 3) * 4;
    const int r1 = (tid + 256) >> 2;
    const int vr = tid >> 4,         vq = (tid & 15) * 4;   // V tile: 16 rows x 64

    ra[0] = *(const float4*)(wb + (size_t)r0 * SS + q0);
    ra[1] = *(const float4*)(wb + (size_t)r1 * SS + q0);
    rv    = *(const float4*)(vb + (size_t)vr * BE + vq);

    for (int k0 = 0; k0 < SS; k0 += 16) {
        cvt_store4(Asm + r0 * PAD + q0, ra[0]);
        cvt_store4(Asm + r1 * PAD + q0, ra[1]);
        cvt_store4(Vsm + vr * PADV + vq, rv);
        __syncthreads();

        if (k0 + 16 < SS) {
            int kn = k0 + 16;
            ra[0] = *(const float4*)(wb + (size_t)r0 * SS + kn + q0);
            ra[1] = *(const float4*)(wb + (size_t)r1 * SS + kn + q0);
            rv    = *(const float4*)(vb + (size_t)(kn + vr) * BE + vq);
        }

        #pragma unroll
        for (int ks = 0; ks < 2; ks++) {
            unsigned a[2][4], bfr[4][2];
            #pragma unroll
            for (int mi = 0; mi < 2; mi++) {
                const unsigned* p = Asm + (wm + mi * 16 + grp) * PAD + ks * 8 + tig;
                a[mi][0] = p[0]; a[mi][1] = p[8 * PAD]; a[mi][2] = p[4]; a[mi][3] = p[8 * PAD + 4];
            }
            #pragma unroll
            for (int ni = 0; ni < 4; ni++) {
                // B element (k,n) from [k][n] layout
                const unsigned* p = Vsm + (ks * 8 + tig) * PADV + wn + ni * 8 + grp;
                bfr[ni][0] = p[0];
                bfr[ni][1] = p[4 * PADV];
            }
            #pragma unroll
            for (int mi = 0; mi < 2; mi++)
                #pragma unroll
                for (int ni = 0; ni < 4; ni++)
                    mma_tf32(acc[mi][ni], a[mi][0], a[mi][1], a[mi][2], a[mi][3],
                             bfr[ni][0], bfr[ni][1]);
        }
        __syncthreads();
    }

    float* ob = g_attn + (size_t)b * EE + h * DD;
    #pragma unroll
    for (int mi = 0; mi < 2; mi++) {
        int t = t0 + wm + mi * 16 + grp;
        #pragma unroll
        for (int ni = 0; ni < 4; ni++) {
            int d = wn + ni * 8 + 2 * tig;
            *(float2*)(ob + (size_t)t * BE + d)       = make_float2(acc[mi][ni][0], acc[mi][ni][1]);
            *(float2*)(ob + (size_t)(t + 8) * BE + d) = make_float2(acc[mi][ni][2], acc[mi][ni][3]);
        }
    }
}

// ============================================================================
// launch
// ============================================================================
extern "C" void kernel_launch(void* const* d_in, const int* in_sizes, int n_in,
                              void* d_out, int out_size)
{
    const float* outs        = (const float*)d_in[2];
    const float* graph_state = (const float*)d_in[3];
    const unsigned char* pad = (const unsigned char*)d_in[4];
    const float* attn_mask   = (const float*)d_in[5];
    const float* strategy_id = (const float*)d_in[6];
    const int*   target_rel  = (const int*)d_in[7];
    const float* Win         = (const float*)d_in[8];
    const float* b_in        = (const float*)d_in[9];
    const float* Wout        = (const float*)d_in[10];
    const float* b_out       = (const float*)d_in[11];

    float* out_f    = (float*)d_out;
    float* out_loss = out_f;
    float* out_outs = out_f + 8;
    float* out_x    = out_f + 8 + (size_t)TT * BB * EE;

    float *qp, *kp, *vp, *ap;
    cudaGetSymbolAddress((void**)&qp, g_q);
    cudaGetSymbolAddress((void**)&kp, g_k);
    cudaGetSymbolAddress((void**)&vp, g_v);
    cudaGetSymbolAddress((void**)&ap, g_attn);

    dim3 gproj(EE / 128, MM / 128);   // (6, 64)

    sgemm_nt_mma<<<gproj, 256>>>(outs,        Win,               b_in,           qp, MM, EE, EE, 0.125f);
    sgemm_nt_mma<<<gproj, 256>>>(graph_state, Win + EE * EE,     b_in + EE,      kp, MM, EE, EE, 1.0f);
    sgemm_nt_mma<<<gproj, 256>>>(graph_state, Win + 2 * EE * EE, b_in + 2 * EE,  vp, MM, EE, EE, 1.0f);

    dim3 glog(SS / 128, TT / 128, BB * HH);   // (8,8,96)
    logits_mma<<<glog, 256>>>(attn_mask, pad);

    dim3 gsm(TT, BB);
    smax_arc_kernel<<<gsm, 256>>>(target_rel);
    finalize_kernel<<<BB, 256>>>(strategy_id, out_loss);

    dim3 gav(TT / 128, BB * HH);
    attnv_mma<<<gav, 256>>>();

    sgemm_nt_mma<<<gproj, 256>>>(ap, Wout, b_out, out_x, MM, EE, EE, 1.0f);

    cudaMemcpyAsync(out_outs, outs, (size_t)TT * BB * EE * sizeof(float),
                    cudaMemcpyDeviceToDevice);
}

// round 11
// speedup vs baseline: 1.0061x; 1.0061x over previous
#include <cuda_runtime.h>
#include <math.h>

#define TT 1024
#define SS 1024
#define BB 8
#define EE 768
#define HH 12
#define DD 64
#define MM (TT*BB)
#define BE (BB*EE)

#define PAD 20          // smem row stride (floats) for 16-wide k tiles -> conflict-free frags
#define PADV 68         // smem row stride for V tiles [16][64]

// ---------------- scratch ----------------
static __device__ float g_q[(size_t)TT * BB * EE];
static __device__ float g_k[(size_t)SS * BB * EE];
static __device__ float g_v[(size_t)SS * BB * EE];
static __device__ float g_w[(size_t)BB * HH * TT * SS];   // logits -> softmax weights
static __device__ float g_attn[(size_t)TT * BB * EE];
static __device__ float g_partBT[BB * TT];                // per (b,t) bce partials

// ---------------- helpers ----------------
__device__ __forceinline__ unsigned f2tf32(float f) {
    unsigned u;
    asm("cvt.rna.tf32.f32 %0, %1;" : "=r"(u) : "f"(f));
    return u;
}

__device__ __forceinline__ void mma_tf32(float c[4],
                                         unsigned a0, unsigned a1, unsigned a2, unsigned a3,
                                         unsigned b0, unsigned b1) {
    asm volatile("mma.sync.aligned.m16n8k8.row.col.f32.tf32.tf32.f32 "
                 "{%0,%1,%2,%3}, {%4,%5,%6,%7}, {%8,%9}, {%0,%1,%2,%3};"
                 : "+f"(c[0]), "+f"(c[1]), "+f"(c[2]), "+f"(c[3])
                 : "r"(a0), "r"(a1), "r"(a2), "r"(a3), "r"(b0), "r"(b1));
}

__device__ __forceinline__ void cvt_store4(unsigned* p, float4 v) {
    uint4 u;
    u.x = f2tf32(v.x); u.y = f2tf32(v.y); u.z = f2tf32(v.z); u.w = f2tf32(v.w);
    *(uint4*)p = u;
}

// ============================================================================
// SGEMM (tf32 mma): C[M,N] = (A[M,K] @ W[N,K]^T + bias) * alpha
// block tile 128x128, BK=16, 8 warps (4x2), warp tile 32x64
// ============================================================================
__global__ __launch_bounds__(256)
void sgemm_nt_mma(const float* __restrict__ A, const float* __restrict__ W,
                  const float* __restrict__ bias, float* __restrict__ C,
                  int M, int N, int K, float alpha)
{
    __shared__ unsigned As[128 * PAD];
    __shared__ unsigned Ws[128 * PAD];

    const int bm = blockIdx.y * 128;
    const int bn = blockIdx.x * 128;
    const int tid  = threadIdx.x;
    const int wid  = tid >> 5;
    const int lane = tid & 31;
    const int wm = (wid >> 1) * 32;
    const int wn = (wid & 1) * 64;
    const int grp = lane >> 2;
    const int tig = lane & 3;

    float acc[2][8][4] = {};
    float4 ra[2], rw[2];

    const int r0 = tid >> 2,        q0 = (tid & 3) * 4;
    const int r1 = (tid + 256) >> 2, q1 = q0;   // second half rows 64..127

    // prefetch k0 = 0
    ra[0] = *(const float4*)(A + (size_t)(bm + r0) * K + q0);
    ra[1] = *(const float4*)(A + (size_t)(bm + r1) * K + q1);
    rw[0] = *(const float4*)(W + (size_t)(bn + r0) * K + q0);
    rw[1] = *(const float4*)(W + (size_t)(bn + r1) * K + q1);

    for (int k0 = 0; k0 < K; k0 += 16) {
        cvt_store4(As + r0 * PAD + q0, ra[0]);
        cvt_store4(As + r1 * PAD + q1, ra[1]);
        cvt_store4(Ws + r0 * PAD + q0, rw[0]);
        cvt_store4(Ws + r1 * PAD + q1, rw[1]);
        __syncthreads();

        if (k0 + 16 < K) {
            int kn = k0 + 16;
            ra[0] = *(const float4*)(A + (size_t)(bm + r0) * K + kn + q0);
            ra[1] = *(const float4*)(A + (size_t)(bm + r1) * K + kn + q1);
            rw[0] = *(const float4*)(W + (size_t)(bn + r0) * K + kn + q0);
            rw[1] = *(const float4*)(W + (size_t)(bn + r1) * K + kn + q1);
        }

        #pragma unroll
        for (int ks = 0; ks < 2; ks++) {
            unsigned a[2][4], b[8][2];
            #pragma unroll
            for (int mi = 0; mi < 2; mi++) {
                const unsigned* p = As + (wm + mi * 16 + grp) * PAD + ks * 8 + tig;
                a[mi][0] = p[0];
                a[mi][1] = p[8 * PAD];
                a[mi][2] = p[4];
                a[mi][3] = p[8 * PAD + 4];
            }
            #pragma unroll
            for (int ni = 0; ni < 8; ni++) {
                const unsigned* p = Ws + (wn + ni * 8 + grp) * PAD + ks * 8 + tig;
                b[ni][0] = p[0];
                b[ni][1] = p[4];
            }
            #pragma unroll
            for (int mi = 0; mi < 2; mi++)
                #pragma unroll
                for (int ni = 0; ni < 8; ni++)
                    mma_tf32(acc[mi][ni], a[mi][0], a[mi][1], a[mi][2], a[mi][3],
                             b[ni][0], b[ni][1]);
        }
        __syncthreads();
    }

    #pragma unroll
    for (int mi = 0; mi < 2; mi++) {
        int row = bm + wm + mi * 16 + grp;
        #pragma unroll
        for (int ni = 0; ni < 8; ni++) {
            int col = bn + wn + ni * 8 + 2 * tig;
            float bv0 = bias[col], bv1 = bias[col + 1];
            float2 v0 = { (acc[mi][ni][0] + bv0) * alpha, (acc[mi][ni][1] + bv1) * alpha };
            float2 v1 = { (acc[mi][ni][2] + bv0) * alpha, (acc[mi][ni][3] + bv1) * alpha };
            *(float2*)(C + (size_t)row * N + col)       = v0;
            *(float2*)(C + (size_t)(row + 8) * N + col) = v1;
        }
    }
}

// ============================================================================
// logits (tf32 mma): g_w[b,h,t,s] = Q.K^T + attn_mask, -inf on padding
// block 128(t) x 128(s), K=D=64 in 4 x BK16 tiles, per (b,h) in z
// ============================================================================
__global__ __launch_bounds__(256)
void logits_mma(const float* __restrict__ attn_mask,
                const unsigned char* __restrict__ pad_mask)
{
    __shared__ unsigned Qs[128 * PAD];
    __shared__ unsigned Ks[128 * PAD];

    const int bh = blockIdx.z;
    const int b  = bh / HH;
    const int h  = bh % HH;
    const int t0 = blockIdx.y * 128;
    const int s0 = blockIdx.x * 128;

    const int tid  = threadIdx.x;
    const int wid  = tid >> 5;
    const int lane = tid & 31;
    const int wm = (wid >> 1) * 32;
    const int wn = (wid & 1) * 64;
    const int grp = lane >> 2;
    const int tig = lane & 3;

    const float* qb = g_q + (size_t)b * EE + h * DD;
    const float* kb = g_k + (size_t)b * EE + h * DD;

    float acc[2][8][4] = {};
    float4 ra[2], rw[2];

    const int r0 = tid >> 2,         q0 = (tid & 3) * 4;
    const int r1 = (tid + 256) >> 2;

    ra[0] = *(const float4*)(qb + (size_t)(t0 + r0) * BE + q0);
    ra[1] = *(const float4*)(qb + (size_t)(t0 + r1) * BE + q0);
    rw[0] = *(const float4*)(kb + (size_t)(s0 + r0) * BE + q0);
    rw[1] = *(const float4*)(kb + (size_t)(s0 + r1) * BE + q0);

    for (int k0 = 0; k0 < DD; k0 += 16) {
        cvt_store4(Qs + r0 * PAD + q0, ra[0]);
        cvt_store4(Qs + r1 * PAD + q0, ra[1]);
        cvt_store4(Ks + r0 * PAD + q0, rw[0]);
        cvt_store4(Ks + r1 * PAD + q0, rw[1]);
        __syncthreads();

        if (k0 + 16 < DD) {
            int kn = k0 + 16;
            ra[0] = *(const float4*)(qb + (size_t)(t0 + r0) * BE + kn + q0);
            ra[1] = *(const float4*)(qb + (size_t)(t0 + r1) * BE + kn + q0);
            rw[0] = *(const float4*)(kb + (size_t)(s0 + r0) * BE + kn + q0);
            rw[1] = *(const float4*)(kb + (size_t)(s0 + r1) * BE + kn + q0);
        }

        #pragma unroll
        for (int ks = 0; ks < 2; ks++) {
            unsigned a[2][4], bfr[8][2];
            #pragma unroll
            for (int mi = 0; mi < 2; mi++) {
                const unsigned* p = Qs + (wm + mi * 16 + grp) * PAD + ks * 8 + tig;
                a[mi][0] = p[0]; a[mi][1] = p[8 * PAD]; a[mi][2] = p[4]; a[mi][3] = p[8 * PAD + 4];
            }
            #pragma unroll
            for (int ni = 0; ni < 8; ni++) {
                const unsigned* p = Ks + (wn + ni * 8 + grp) * PAD + ks * 8 + tig;
                bfr[ni][0] = p[0]; bfr[ni][1] = p[4];
            }
            #pragma unroll
            for (int mi = 0; mi < 2; mi++)
                #pragma unroll
                for (int ni = 0; ni < 8; ni++)
                    mma_tf32(acc[mi][ni], a[mi][0], a[mi][1], a[mi][2], a[mi][3],
                             bfr[ni][0], bfr[ni][1]);
        }
        __syncthreads();
    }

    const float NEG = __int_as_float(0xff800000);
    float* out = g_w + (size_t)bh * TT * SS;

    #pragma unroll
    for (int mi = 0; mi < 2; mi++) {
        int t = t0 + wm + mi * 16 + grp;
        #pragma unroll
        for (int ni = 0; ni < 8; ni++) {
            int s = s0 + wn + ni * 8 + 2 * tig;
            bool p0 = pad_mask[b * SS + s];
            bool p1 = pad_mask[b * SS + s + 1];
            float2 v0, v1;
            v0.x = p0 ? NEG : acc[mi][ni][0] + attn_mask[(size_t)t * SS + s];
            v0.y = p1 ? NEG : acc[mi][ni][1] + attn_mask[(size_t)t * SS + s + 1];
            v1.x = p0 ? NEG : acc[mi][ni][2] + attn_mask[(size_t)(t + 8) * SS + s];
            v1.y = p1 ? NEG : acc[mi][ni][3] + attn_mask[(size_t)(t + 8) * SS + s + 1];
            *(float2*)(out + (size_t)t * SS + s)       = v0;
            *(float2*)(out + (size_t)(t + 8) * SS + s) = v1;
        }
    }
}

// ============================================================================
// Fused softmax (in-place on g_w, per head) + head-max + BCE per (b,t)
// ============================================================================
__global__ __launch_bounds__(256)
void smax_arc_kernel(const int* __restrict__ target_rel)
{
    const int t = blockIdx.x;
    const int b = blockIdx.y;
    const int tid  = threadIdx.x;
    const int lane = tid & 31;
    const int wid  = tid >> 5;
    __shared__ float red[40];

    float hm0 = 0.f, hm1 = 0.f, hm2 = 0.f, hm3 = 0.f;

    for (int h = 0; h < HH; h++) {
        float* row = g_w + (((size_t)(b * HH + h)) * TT + t) * SS;
        float4 v = ((float4*)row)[tid];

        float m = fmaxf(fmaxf(v.x, v.y), fmaxf(v.z, v.w));
        #pragma unroll
        for (int o = 16; o > 0; o >>= 1) m = fmaxf(m, __shfl_xor_sync(~0u, m, o));
        if (lane == 0) red[wid] = m;
        __syncthreads();
        if (wid == 0) {
            float mm = red[lane & 7];
            #pragma unroll
            for (int o = 4; o > 0; o >>= 1) mm = fmaxf(mm, __shfl_xor_sync(~0u, mm, o));
            if (lane == 0) red[32] = mm;
        }
        __syncthreads();
        m = red[32];

        v.x = __expf(v.x - m); v.y = __expf(v.y - m);
        v.z = __expf(v.z - m); v.w = __expf(v.w - m);
        float s = v.x + v.y + v.z + v.w;
        #pragma unroll
        for (int o = 16; o > 0; o >>= 1) s += __shfl_xor_sync(~0u, s, o);
        if (lane == 0) red[wid + 8] = s;
        __syncthreads();
        if (wid == 0) {
            float ss = red[8 + (lane & 7)];
            #pragma unroll
            for (int o = 4; o > 0; o >>= 1) ss += __shfl_xor_sync(~0u, ss, o);
            if (lane == 0) red[33] = ss;
        }
        __syncthreads();
        float inv = 1.f / red[33];

        v.x *= inv; v.y *= inv; v.z *= inv; v.w *= inv;
        ((float4*)row)[tid] = v;
        hm0 = fmaxf(hm0, v.x); hm1 = fmaxf(hm1, v.y);
        hm2 = fmaxf(hm2, v.z); hm3 = fmaxf(hm3, v.w);
        __syncthreads();
    }

    // BCE: rel==0 -> 0; rel==1 -> -max(log(w),-100); rel==2 -> -max(log1p(-w),-100)
    int4 rel = ((const int4*)(target_rel + ((size_t)t * BB + b) * SS))[tid];
    float sum = 0.f;
    if (rel.x == 1) sum -= fmaxf(logf(hm0), -100.f); else if (rel.x == 2) sum -= fmaxf(log1pf(-hm0), -100.f);
    if (rel.y == 1) sum -= fmaxf(logf(hm1), -100.f); else if (rel.y == 2) sum -= fmaxf(log1pf(-hm1), -100.f);
    if (rel.z == 1) sum -= fmaxf(logf(hm2), -100.f); else if (rel.z == 2) sum -= fmaxf(log1pf(-hm2), -100.f);
    if (rel.w == 1) sum -= fmaxf(logf(hm3), -100.f); else if (rel.w == 2) sum -= fmaxf(log1pf(-hm3), -100.f);

    #pragma unroll
    for (int o = 16; o > 0; o >>= 1) sum += __shfl_xor_sync(~0u, sum, o);
    if (lane == 0) red[wid + 16] = sum;
    __syncthreads();
    if (wid == 0) {
        float ss = red[16 + (lane & 7)];
        #pragma unroll
        for (int o = 4; o > 0; o >>= 1) ss += __shfl_xor_sync(~0u, ss, o);
        if (lane == 0) g_partBT[b * TT + t] = ss;
    }
}

__global__ void finalize_kernel(const float* __restrict__ strategy_id,
                                float* __restrict__ out)
{
    __shared__ float red[256];
    int b = blockIdx.x;
    int tid = threadIdx.x;
    float s = 0.f;
    for (int i = tid; i < TT; i += 256) s += g_partBT[b * TT + i];
    red[tid] = s; __syncthreads();
    #pragma unroll
    for (int o = 128; o > 0; o >>= 1) {
        if (tid < o) red[tid] += red[tid + o];
        __syncthreads();
    }
    if (tid == 0) out[b] = red[0] * strategy_id[b];
}

// ============================================================================
// attn·V (tf32 mma): g_attn[t,b,h*64+d] = sum_s w[b,h,t,s] * v[s,b,h,d]
// block 128(t) x 64(d), K=S=1024 in BK16 tiles, per (b,h) in y
// warp tile 32x32 (8 warps, 4x2)
// ============================================================================
__global__ __launch_bounds__(256)
void attnv_mma()
{
    __shared__ unsigned Asm[128 * PAD];   // weights [t][k]
    __shared__ unsigned Vsm[16 * PADV];   // V tile [k(s)][n(d)]

    const int bh = blockIdx.y;
    const int b  = bh / HH;
    const int h  = bh % HH;
    const int t0 = blockIdx.x * 128;

    const int tid  = threadIdx.x;
    const int wid  = tid >> 5;
    const int lane = tid & 31;
    const int wm = (wid >> 1) * 32;
    const int wn = (wid & 1) * 32;
    const int grp = lane >> 2;
    const int tig = lane & 3;

    const float* wb = g_w + ((size_t)bh * TT + t0) * SS;
    const float* vb = g_v + (size_t)b * EE + h * DD;

    float acc[2][4][4] = {};
    float4 ra[2], rv;

    const int r0 = tid >> 2,         q0 = (tid & 3) * 4;
    const int r1 = (tid + 256) >> 2;
    const int vr = tid >> 4,         vq = (tid & 15) * 4;   // V tile: 16 rows x 64

    ra[0] = *(const float4*)(wb + (size_t)r0 * SS + q0);
    ra[1] = *(const float4*)(wb + (size_t)r1 * SS + q0);
    rv    = *(const float4*)(vb + (size_t)vr * BE + vq);

    for (int k0 = 0; k0 < SS; k0 += 16) {
        cvt_store4(Asm + r0 * PAD + q0, ra[0]);
        cvt_store4(Asm + r1 * PAD + q0, ra[1]);
        cvt_store4(Vsm + vr * PADV + vq, rv);
        __syncthreads();

        if (k0 + 16 < SS) {
            int kn = k0 + 16;
            ra[0] = *(const float4*)(wb + (size_t)r0 * SS + kn + q0);
            ra[1] = *(const float4*)(wb + (size_t)r1 * SS + kn + q0);
            rv    = *(const float4*)(vb + (size_t)(kn + vr) * BE + vq);
        }

        #pragma unroll
        for (int ks = 0; ks < 2; ks++) {
            unsigned a[2][4], bfr[4][2];
            #pragma unroll
            for (int mi = 0; mi < 2; mi++) {
                const unsigned* p = Asm + (wm + mi * 16 + grp) * PAD + ks * 8 + tig;
                a[mi][0] = p[0]; a[mi][1] = p[8 * PAD]; a[mi][2] = p[4]; a[mi][3] = p[8 * PAD + 4];
            }
            #pragma unroll
            for (int ni = 0; ni < 4; ni++) {
                // B element (k,n) from [k][n] layout
                const unsigned* p = Vsm + (ks * 8 + tig) * PADV + wn + ni * 8 + grp;
                bfr[ni][0] = p[0];
                bfr[ni][1] = p[4 * PADV];
            }
            #pragma unroll
            for (int mi = 0; mi < 2; mi++)
                #pragma unroll
                for (int ni = 0; ni < 4; ni++)
                    mma_tf32(acc[mi][ni], a[mi][0], a[mi][1], a[mi][2], a[mi][3],
                             bfr[ni][0], bfr[ni][1]);
        }
        __syncthreads();
    }

    float* ob = g_attn + (size_t)b * EE + h * DD;
    #pragma unroll
    for (int mi = 0; mi < 2; mi++) {
        int t = t0 + wm + mi * 16 + grp;
        #pragma unroll
        for (int ni = 0; ni < 4; ni++) {
            int d = wn + ni * 8 + 2 * tig;
            *(float2*)(ob + (size_t)t * BE + d)       = make_float2(acc[mi][ni][0], acc[mi][ni][1]);
            *(float2*)(ob + (size_t)(t + 8) * BE + d) = make_float2(acc[mi][ni][2], acc[mi][ni][3]);
        }
    }
}

// ============================================================================
// launch
// ============================================================================
extern "C" void kernel_launch(void* const* d_in, const int* in_sizes, int n_in,
                              void* d_out, int out_size)
{
    const float* outs        = (const float*)d_in[2];
    const float* graph_state = (const float*)d_in[3];
    const unsigned char* pad = (const unsigned char*)d_in[4];
    const float* attn_mask   = (const float*)d_in[5];
    const float* strategy_id = (const float*)d_in[6];
    const int*   target_rel  = (const int*)d_in[7];
    const float* Win         = (const float*)d_in[8];
    const float* b_in        = (const float*)d_in[9];
    const float* Wout        = (const float*)d_in[10];
    const float* b_out       = (const float*)d_in[11];

    float* out_f    = (float*)d_out;
    float* out_loss = out_f;
    float* out_outs = out_f + 8;
    float* out_x    = out_f + 8 + (size_t)TT * BB * EE;

    float *qp, *kp, *vp, *ap;
    cudaGetSymbolAddress((void**)&qp, g_q);
    cudaGetSymbolAddress((void**)&kp, g_k);
    cudaGetSymbolAddress((void**)&vp, g_v);
    cudaGetSymbolAddress((void**)&ap, g_attn);

    dim3 gproj(EE / 128, MM / 128);   // (6, 64)

    sgemm_nt_mma<<<gproj, 256>>>(outs,        Win,               b_in,           qp, MM, EE, EE, 0.125f);
    sgemm_nt_mma<<<gproj, 256>>>(graph_state, Win + EE * EE,     b_in + EE,      kp, MM, EE, EE, 1.0f);
    sgemm_nt_mma<<<gproj, 256>>>(graph_state, Win + 2 * EE * EE, b_in + 2 * EE,  vp, MM, EE, EE, 1.0f);

    dim3 glog(SS / 128, TT / 128, BB * HH);   // (8,8,96)
    logits_mma<<<glog, 256>>>(attn_mask, pad);

    dim3 gsm(TT, BB);
    smax_arc_kernel<<<gsm, 256>>>(target_rel);
    finalize_kernel<<<BB, 256>>>(strategy_id, out_loss);

    dim3 gav(TT / 128, BB * HH);
    attnv_mma<<<gav, 256>>>();

    sgemm_nt_mma<<<gproj, 256>>>(ap, Wout, b_out, out_x, MM, EE, EE, 1.0f);

    cudaMemcpyAsync(out_outs, outs, (size_t)TT * BB * EE * sizeof(float),
                    cudaMemcpyDeviceToDevice);
}

// round 12
// speedup vs baseline: 1.0063x; 1.0001x over previous
#include <cuda_runtime.h>
#include <math.h>

#define TT 1024
#define SS 1024
#define BB 8
#define EE 768
#define HH 12
#define DD 64
#define MM (TT*BB)
#define BE (BB*EE)

#define PAD 20          // smem row stride (floats) for 16-wide k tiles -> conflict-free frags
#define PADV 68         // smem row stride for V tiles [16][64]

// ---------------- scratch ----------------
static __device__ float g_q[(size_t)TT * BB * EE];
static __device__ float g_k[(size_t)SS * BB * EE];
static __device__ float g_v[(size_t)SS * BB * EE];
static __device__ float g_w[(size_t)BB * HH * TT * SS];   // logits -> softmax weights
static __device__ float g_attn[(size_t)TT * BB * EE];
static __device__ float g_partBT[BB * TT];                // per (b,t) bce partials

// ---------------- helpers ----------------
__device__ __forceinline__ unsigned f2tf32(float f) {
    unsigned u;
    asm("cvt.rna.tf32.f32 %0, %1;" : "=r"(u) : "f"(f));
    return u;
}

__device__ __forceinline__ void mma_tf32(float c[4],
                                         unsigned a0, unsigned a1, unsigned a2, unsigned a3,
                                         unsigned b0, unsigned b1) {
    asm volatile("mma.sync.aligned.m16n8k8.row.col.f32.tf32.tf32.f32 "
                 "{%0,%1,%2,%3}, {%4,%5,%6,%7}, {%8,%9}, {%0,%1,%2,%3};"
                 : "+f"(c[0]), "+f"(c[1]), "+f"(c[2]), "+f"(c[3])
                 : "r"(a0), "r"(a1), "r"(a2), "r"(a3), "r"(b0), "r"(b1));
}

__device__ __forceinline__ void cvt_store4(unsigned* p, float4 v) {
    uint4 u;
    u.x = f2tf32(v.x); u.y = f2tf32(v.y); u.z = f2tf32(v.z); u.w = f2tf32(v.w);
    *(uint4*)p = u;
}

// ============================================================================
// SGEMM (tf32 mma): C[M,N] = (A[M,K] @ W[N,K]^T + bias) * alpha
// block tile 128x128, BK=16, 8 warps (4x2), warp tile 32x64
// ============================================================================
__global__ __launch_bounds__(256)
void sgemm_nt_mma(const float* __restrict__ A, const float* __restrict__ W,
                  const float* __restrict__ bias, float* __restrict__ C,
                  int M, int N, int K, float alpha)
{
    __shared__ unsigned As[128 * PAD];
    __shared__ unsigned Ws[128 * PAD];

    const int bm = blockIdx.y * 128;
    const int bn = blockIdx.x * 128;
    const int tid  = threadIdx.x;
    const int wid  = tid >> 5;
    const int lane = tid & 31;
    const int wm = (wid >> 1) * 32;
    const int wn = (wid & 1) * 64;
    const int grp = lane >> 2;
    const int tig = lane & 3;

    float acc[2][8][4] = {};
    float4 ra[2], rw[2];

    const int r0 = tid >> 2,        q0 = (tid & 3) * 4;
    const int r1 = (tid + 256) >> 2, q1 = q0;   // second half rows 64..127

    // prefetch k0 = 0
    ra[0] = *(const float4*)(A + (size_t)(bm + r0) * K + q0);
    ra[1] = *(const float4*)(A + (size_t)(bm + r1) * K + q1);
    rw[0] = *(const float4*)(W + (size_t)(bn + r0) * K + q0);
    rw[1] = *(const float4*)(W + (size_t)(bn + r1) * K + q1);

    for (int k0 = 0; k0 < K; k0 += 16) {
        cvt_store4(As + r0 * PAD + q0, ra[0]);
        cvt_store4(As + r1 * PAD + q1, ra[1]);
        cvt_store4(Ws + r0 * PAD + q0, rw[0]);
        cvt_store4(Ws + r1 * PAD + q1, rw[1]);
        __syncthreads();

        if (k0 + 16 < K) {
            int kn = k0 + 16;
            ra[0] = *(const float4*)(A + (size_t)(bm + r0) * K + kn + q0);
            ra[1] = *(const float4*)(A + (size_t)(bm + r1) * K + kn + q1);
            rw[0] = *(const float4*)(W + (size_t)(bn + r0) * K + kn + q0);
            rw[1] = *(const float4*)(W + (size_t)(bn + r1) * K + kn + q1);
        }

        #pragma unroll
        for (int ks = 0; ks < 2; ks++) {
            unsigned a[2][4], b[8][2];
            #pragma unroll
            for (int mi = 0; mi < 2; mi++) {
                const unsigned* p = As + (wm + mi * 16 + grp) * PAD + ks * 8 + tig;
                a[mi][0] = p[0];
                a[mi][1] = p[8 * PAD];
                a[mi][2] = p[4];
                a[mi][3] = p[8 * PAD + 4];
            }
            #pragma unroll
            for (int ni = 0; ni < 8; ni++) {
                const unsigned* p = Ws + (wn + ni * 8 + grp) * PAD + ks * 8 + tig;
                b[ni][0] = p[0];
                b[ni][1] = p[4];
            }
            #pragma unroll
            for (int mi = 0; mi < 2; mi++)
                #pragma unroll
                for (int ni = 0; ni < 8; ni++)
                    mma_tf32(acc[mi][ni], a[mi][0], a[mi][1], a[mi][2], a[mi][3],
                             b[ni][0], b[ni][1]);
        }
        __syncthreads();
    }

    #pragma unroll
    for (int mi = 0; mi < 2; mi++) {
        int row = bm + wm + mi * 16 + grp;
        #pragma unroll
        for (int ni = 0; ni < 8; ni++) {
            int col = bn + wn + ni * 8 + 2 * tig;
            float bv0 = bias[col], bv1 = bias[col + 1];
            float2 v0 = { (acc[mi][ni][0] + bv0) * alpha, (acc[mi][ni][1] + bv1) * alpha };
            float2 v1 = { (acc[mi][ni][2] + bv0) * alpha, (acc[mi][ni][3] + bv1) * alpha };
            *(float2*)(C + (size_t)row * N + col)       = v0;
            *(float2*)(C + (size_t)(row + 8) * N + col) = v1;
        }
    }
}

// ============================================================================
// logits (tf32 mma): g_w[b,h,t,s] = Q.K^T + attn_mask, -inf on padding
// block 128(t) x 128(s), K=D=64 in 4 x BK16 tiles, per (b,h) in z
// ============================================================================
__global__ __launch_bounds__(256)
void logits_mma(const float* __restrict__ attn_mask,
                const unsigned char* __restrict__ pad_mask)
{
    __shared__ unsigned Qs[128 * PAD];
    __shared__ unsigned Ks[128 * PAD];

    const int bh = blockIdx.z;
    const int b  = bh / HH;
    const int h  = bh % HH;
    const int t0 = blockIdx.y * 128;
    const int s0 = blockIdx.x * 128;

    const int tid  = threadIdx.x;
    const int wid  = tid >> 5;
    const int lane = tid & 31;
    const int wm = (wid >> 1) * 32;
    const int wn = (wid & 1) * 64;
    const int grp = lane >> 2;
    const int tig = lane & 3;

    const float* qb = g_q + (size_t)b * EE + h * DD;
    const float* kb = g_k + (size_t)b * EE + h * DD;

    float acc[2][8][4] = {};
    float4 ra[2], rw[2];

    const int r0 = tid >> 2,         q0 = (tid & 3) * 4;
    const int r1 = (tid + 256) >> 2;

    ra[0] = *(const float4*)(qb + (size_t)(t0 + r0) * BE + q0);
    ra[1] = *(const float4*)(qb + (size_t)(t0 + r1) * BE + q0);
    rw[0] = *(const float4*)(kb + (size_t)(s0 + r0) * BE + q0);
    rw[1] = *(const float4*)(kb + (size_t)(s0 + r1) * BE + q0);

    for (int k0 = 0; k0 < DD; k0 += 16) {
        cvt_store4(Qs + r0 * PAD + q0, ra[0]);
        cvt_store4(Qs + r1 * PAD + q0, ra[1]);
        cvt_store4(Ks + r0 * PAD + q0, rw[0]);
        cvt_store4(Ks + r1 * PAD + q0, rw[1]);
        __syncthreads();

        if (k0 + 16 < DD) {
            int kn = k0 + 16;
            ra[0] = *(const float4*)(qb + (size_t)(t0 + r0) * BE + kn + q0);
            ra[1] = *(const float4*)(qb + (size_t)(t0 + r1) * BE + kn + q0);
            rw[0] = *(const float4*)(kb + (size_t)(s0 + r0) * BE + kn + q0);
            rw[1] = *(const float4*)(kb + (size_t)(s0 + r1) * BE + kn + q0);
        }

        #pragma unroll
        for (int ks = 0; ks < 2; ks++) {
            unsigned a[2][4], bfr[8][2];
            #pragma unroll
            for (int mi = 0; mi < 2; mi++) {
                const unsigned* p = Qs + (wm + mi * 16 + grp) * PAD + ks * 8 + tig;
                a[mi][0] = p[0]; a[mi][1] = p[8 * PAD]; a[mi][2] = p[4]; a[mi][3] = p[8 * PAD + 4];
            }
            #pragma unroll
            for (int ni = 0; ni < 8; ni++) {
                const unsigned* p = Ks + (wn + ni * 8 + grp) * PAD + ks * 8 + tig;
                bfr[ni][0] = p[0]; bfr[ni][1] = p[4];
            }
            #pragma unroll
            for (int mi = 0; mi < 2; mi++)
                #pragma unroll
                for (int ni = 0; ni < 8; ni++)
                    mma_tf32(acc[mi][ni], a[mi][0], a[mi][1], a[mi][2], a[mi][3],
                             bfr[ni][0], bfr[ni][1]);
        }
        __syncthreads();
    }

    const float NEG = __int_as_float(0xff800000);
    float* out = g_w + (size_t)bh * TT * SS;

    #pragma unroll
    for (int mi = 0; mi < 2; mi++) {
        int t = t0 + wm + mi * 16 + grp;
        #pragma unroll
        for (int ni = 0; ni < 8; ni++) {
            int s = s0 + wn + ni * 8 + 2 * tig;
            bool p0 = pad_mask[b * SS + s];
            bool p1 = pad_mask[b * SS + s + 1];
            float2 v0, v1;
            v0.x = p0 ? NEG : acc[mi][ni][0] + attn_mask[(size_t)t * SS + s];
            v0.y = p1 ? NEG : acc[mi][ni][1] + attn_mask[(size_t)t * SS + s + 1];
            v1.x = p0 ? NEG : acc[mi][ni][2] + attn_mask[(size_t)(t + 8) * SS + s];
            v1.y = p1 ? NEG : acc[mi][ni][3] + attn_mask[(size_t)(t + 8) * SS + s + 1];
            *(float2*)(out + (size_t)t * SS + s)       = v0;
            *(float2*)(out + (size_t)(t + 8) * SS + s) = v1;
        }
    }
}

// ============================================================================
// Fused softmax (in-place on g_w, per head) + head-max + BCE per (b,t)
// ============================================================================
__global__ __launch_bounds__(256)
void smax_arc_kernel(const int* __restrict__ target_rel)
{
    const int t = blockIdx.x;
    const int b = blockIdx.y;
    const int tid  = threadIdx.x;
    const int lane = tid & 31;
    const int wid  = tid >> 5;
    __shared__ float red[40];

    float hm0 = 0.f, hm1 = 0.f, hm2 = 0.f, hm3 = 0.f;

    for (int h = 0; h < HH; h++) {
        float* row = g_w + (((size_t)(b * HH + h)) * TT + t) * SS;
        float4 v = ((float4*)row)[tid];

        float m = fmaxf(fmaxf(v.x, v.y), fmaxf(v.z, v.w));
        #pragma unroll
        for (int o = 16; o > 0; o >>= 1) m = fmaxf(m, __shfl_xor_sync(~0u, m, o));
        if (lane == 0) red[wid] = m;
        __syncthreads();
        if (wid == 0) {
            float mm = red[lane & 7];
            #pragma unroll
            for (int o = 4; o > 0; o >>= 1) mm = fmaxf(mm, __shfl_xor_sync(~0u, mm, o));
            if (lane == 0) red[32] = mm;
        }
        __syncthreads();
        m = red[32];

        v.x = __expf(v.x - m); v.y = __expf(v.y - m);
        v.z = __expf(v.z - m); v.w = __expf(v.w - m);
        float s = v.x + v.y + v.z + v.w;
        #pragma unroll
        for (int o = 16; o > 0; o >>= 1) s += __shfl_xor_sync(~0u, s, o);
        if (lane == 0) red[wid + 8] = s;
        __syncthreads();
        if (wid == 0) {
            float ss = red[8 + (lane & 7)];
            #pragma unroll
            for (int o = 4; o > 0; o >>= 1) ss += __shfl_xor_sync(~0u, ss, o);
            if (lane == 0) red[33] = ss;
        }
        __syncthreads();
        float inv = 1.f / red[33];

        v.x *= inv; v.y *= inv; v.z *= inv; v.w *= inv;
        ((float4*)row)[tid] = v;
        hm0 = fmaxf(hm0, v.x); hm1 = fmaxf(hm1, v.y);
        hm2 = fmaxf(hm2, v.z); hm3 = fmaxf(hm3, v.w);
        __syncthreads();
    }

    // BCE: rel==0 -> 0; rel==1 -> -max(log(w),-100); rel==2 -> -max(log1p(-w),-100)
    int4 rel = ((const int4*)(target_rel + ((size_t)t * BB + b) * SS))[tid];
    float sum = 0.f;
    if (rel.x == 1) sum -= fmaxf(logf(hm0), -100.f); else if (rel.x == 2) sum -= fmaxf(log1pf(-hm0), -100.f);
    if (rel.y == 1) sum -= fmaxf(logf(hm1), -100.f); else if (rel.y == 2) sum -= fmaxf(log1pf(-hm1), -100.f);
    if (rel.z == 1) sum -= fmaxf(logf(hm2), -100.f); else if (rel.z == 2) sum -= fmaxf(log1pf(-hm2), -100.f);
    if (rel.w == 1) sum -= fmaxf(logf(hm3), -100.f); else if (rel.w == 2) sum -= fmaxf(log1pf(-hm3), -100.f);

    #pragma unroll
    for (int o = 16; o > 0; o >>= 1) sum += __shfl_xor_sync(~0u, sum, o);
    if (lane == 0) red[wid + 16] = sum;
    __syncthreads();
    if (wid == 0) {
        float ss = red[16 + (lane & 7)];
        #pragma unroll
        for (int o = 4; o > 0; o >>= 1) ss += __shfl_xor_sync(~0u, ss, o);
        if (lane == 0) g_partBT[b * TT + t] = ss;
    }
}

__global__ void finalize_kernel(const float* __restrict__ strategy_id,
                                float* __restrict__ out)
{
    __shared__ float red[256];
    int b = blockIdx.x;
    int tid = threadIdx.x;
    float s = 0.f;
    for (int i = tid; i < TT; i += 256) s += g_partBT[b * TT + i];
    red[tid] = s; __syncthreads();
    #pragma unroll
    for (int o = 128; o > 0; o >>= 1) {
        if (tid < o) red[tid] += red[tid + o];
        __syncthreads();
    }
    if (tid == 0) out[b] = red[0] * strategy_id[b];
}

// ============================================================================
// attn·V (tf32 mma): g_attn[t,b,h*64+d] = sum_s w[b,h,t,s] * v[s,b,h,d]
// block 128(t) x 64(d), K=S=1024 in BK16 tiles, per (b,h) in y
// warp tile 32x32 (8 warps, 4x2)
// ============================================================================
__global__ __launch_bounds__(256)
void attnv_mma()
{
    __shared__ unsigned Asm[128 * PAD];   // weights [t][k]
    __shared__ unsigned Vsm[16 * PADV];   // V tile [k(s)][n(d)]

    const int bh = blockIdx.y;
    const int b  = bh / HH;
    const int h  = bh % HH;
    const int t0 = blockIdx.x * 128;

    const int tid  = threadIdx.x;
    const int wid  = tid >> 5;
    const int lane = tid & 31;
    const int wm = (wid >> 1) * 32;
    const int wn = (wid & 1) * 32;
    const int grp = lane >> 2;
    const int tig = lane & 3;

    const float* wb = g_w + ((size_t)bh * TT + t0) * SS;
    const float* vb = g_v + (size_t)b * EE + h * DD;

    float acc[2][4][4] = {};
    float4 ra[2], rv;

    const int r0 = tid >> 2,         q0 = (tid & 3) * 4;
    const int r1 = (tid + 256) >> 2;
    const int vr = tid >> 4,         vq = (tid & 15) * 4;   // V tile: 16 rows x 64

    ra[0] = *(const float4*)(wb + (size_t)r0 * SS + q0);
    ra[1] = *(const float4*)(wb + (size_t)r1 * SS + q0);
    rv    = *(const float4*)(vb + (size_t)vr * BE + vq);

    for (int k0 = 0; k0 < SS; k0 += 16) {
        cvt_store4(Asm + r0 * PAD + q0, ra[0]);
        cvt_store4(Asm + r1 * PAD + q0, ra[1]);
        cvt_store4(Vsm + vr * PADV + vq, rv);
        __syncthreads();

        if (k0 + 16 < SS) {
            int kn = k0 + 16;
            ra[0] = *(const float4*)(wb + (size_t)r0 * SS + kn + q0);
            ra[1] = *(const float4*)(wb + (size_t)r1 * SS + kn + q0);
            rv    = *(const float4*)(vb + (size_t)(kn + vr) * BE + vq);
        }

        #pragma unroll
        for (int ks = 0; ks < 2; ks++) {
            unsigned a[2][4], bfr[4][2];
            #pragma unroll
            for (int mi = 0; mi < 2; mi++) {
                const unsigned* p = Asm + (wm + mi * 16 + grp) * PAD + ks * 8 + tig;
                a[mi][0] = p[0]; a[mi][1] = p[8 * PAD]; a[mi][2] = p[4]; a[mi][3] = p[8 * PAD + 4];
            }
            #pragma unroll
            for (int ni = 0; ni < 4; ni++) {
                // B element (k,n) from [k][n] layout
                const unsigned* p = Vsm + (ks * 8 + tig) * PADV + wn + ni * 8 + grp;
                bfr[ni][0] = p[0];
                bfr[ni][1] = p[4 * PADV];
            }
            #pragma unroll
            for (int mi = 0; mi < 2; mi++)
                #pragma unroll
                for (int ni = 0; ni < 4; ni++)
                    mma_tf32(acc[mi][ni], a[mi][0], a[mi][1], a[mi][2], a[mi][3],
                             bfr[ni][0], bfr[ni][1]);
        }
        __syncthreads();
    }

    float* ob = g_attn + (size_t)b * EE + h * DD;
    #pragma unroll
    for (int mi = 0; mi < 2; mi++) {
        int t = t0 + wm + mi * 16 + grp;
        #pragma unroll
        for (int ni = 0; ni < 4; ni++) {
            int d = wn + ni * 8 + 2 * tig;
            *(float2*)(ob + (size_t)t * BE + d)       = make_float2(acc[mi][ni][0], acc[mi][ni][1]);
            *(float2*)(ob + (size_t)(t + 8) * BE + d) = make_float2(acc[mi][ni][2], acc[mi][ni][3]);
        }
    }
}

// ============================================================================
// launch
// ============================================================================
extern "C" void kernel_launch(void* const* d_in, const int* in_sizes, int n_in,
                              void* d_out, int out_size)
{
    const float* outs        = (const float*)d_in[2];
    const float* graph_state = (const float*)d_in[3];
    const unsigned char* pad = (const unsigned char*)d_in[4];
    const float* attn_mask   = (const float*)d_in[5];
    const float* strategy_id = (const float*)d_in[6];
    const int*   target_rel  = (const int*)d_in[7];
    const float* Win         = (const float*)d_in[8];
    const float* b_in        = (const float*)d_in[9];
    const float* Wout        = (const float*)d_in[10];
    const float* b_out       = (const float*)d_in[11];

    float* out_f    = (float*)d_out;
    float* out_loss = out_f;
    float* out_outs = out_f + 8;
    float* out_x    = out_f + 8 + (size_t)TT * BB * EE;

    float *qp, *kp, *vp, *ap;
    cudaGetSymbolAddress((void**)&qp, g_q);
    cudaGetSymbolAddress((void**)&kp, g_k);
    cudaGetSymbolAddress((void**)&vp, g_v);
    cudaGetSymbolAddress((void**)&ap, g_attn);

    dim3 gproj(EE / 128, MM / 128);   // (6, 64)

    sgemm_nt_mma<<<gproj, 256>>>(outs,        Win,               b_in,           qp, MM, EE, EE, 0.125f);
    sgemm_nt_mma<<<gproj, 256>>>(graph_state, Win + EE * EE,     b_in + EE,      kp, MM, EE, EE, 1.0f);
    sgemm_nt_mma<<<gproj, 256>>>(graph_state, Win + 2 * EE * EE, b_in + 2 * EE,  vp, MM, EE, EE, 1.0f);

    dim3 glog(SS / 128, TT / 128, BB * HH);   // (8,8,96)
    logits_mma<<<glog, 256>>>(attn_mask, pad);

    dim3 gsm(TT, BB);
    smax_arc_kernel<<<gsm, 256>>>(target_rel);
    finalize_kernel<<<BB, 256>>>(strategy_id, out_loss);

    dim3 gav(TT / 128, BB * HH);
    attnv_mma<<<gav, 256>>>();

    sgemm_nt_mma<<<gproj, 256>>>(ap, Wout, b_out, out_x, MM, EE, EE, 1.0f);

    cudaMemcpyAsync(out_outs, outs, (size_t)TT * BB * EE * sizeof(float),
                    cudaMemcpyDeviceToDevice);
}

// round 13
// speedup vs baseline: 1.0066x; 1.0004x over previous
#include <cuda_runtime.h>
#include <math.h>

#define TT 1024
#define SS 1024
#define BB 8
#define EE 768
#define HH 12
#define DD 64
#define MM (TT*BB)
#define BE (BB*EE)

#define PAD 20          // smem row stride (floats) for 16-wide k tiles -> conflict-free frags
#define PADV 68         // smem row stride for V tiles [16][64]

// ---------------- scratch ----------------
static __device__ float g_q[(size_t)TT * BB * EE];
static __device__ float g_k[(size_t)SS * BB * EE];
static __device__ float g_v[(size_t)SS * BB * EE];
static __device__ float g_w[(size_t)BB * HH * TT * SS];   // logits -> softmax weights
static __device__ float g_attn[(size_t)TT * BB * EE];
static __device__ float g_partBT[BB * TT];                // per (b,t) bce partials

// ---------------- helpers ----------------
__device__ __forceinline__ unsigned f2tf32(float f) {
    unsigned u;
    asm("cvt.rna.tf32.f32 %0, %1;" : "=r"(u) : "f"(f));
    return u;
}

__device__ __forceinline__ void mma_tf32(float c[4],
                                         unsigned a0, unsigned a1, unsigned a2, unsigned a3,
                                         unsigned b0, unsigned b1) {
    asm volatile("mma.sync.aligned.m16n8k8.row.col.f32.tf32.tf32.f32 "
                 "{%0,%1,%2,%3}, {%4,%5,%6,%7}, {%8,%9}, {%0,%1,%2,%3};"
                 : "+f"(c[0]), "+f"(c[1]), "+f"(c[2]), "+f"(c[3])
                 : "r"(a0), "r"(a1), "r"(a2), "r"(a3), "r"(b0), "r"(b1));
}

__device__ __forceinline__ void cvt_store4(unsigned* p, float4 v) {
    uint4 u;
    u.x = f2tf32(v.x); u.y = f2tf32(v.y); u.z = f2tf32(v.z); u.w = f2tf32(v.w);
    *(uint4*)p = u;
}

// ============================================================================
// SGEMM (tf32 mma): C[M,N] = (A[M,K] @ W[N,K]^T + bias) * alpha
// block tile 128x128, BK=16, 8 warps (4x2), warp tile 32x64
// ============================================================================
__global__ __launch_bounds__(256)
void sgemm_nt_mma(const float* __restrict__ A, const float* __restrict__ W,
                  const float* __restrict__ bias, float* __restrict__ C,
                  int M, int N, int K, float alpha)
{
    __shared__ unsigned As[128 * PAD];
    __shared__ unsigned Ws[128 * PAD];

    const int bm = blockIdx.y * 128;
    const int bn = blockIdx.x * 128;
    const int tid  = threadIdx.x;
    const int wid  = tid >> 5;
    const int lane = tid & 31;
    const int wm = (wid >> 1) * 32;
    const int wn = (wid & 1) * 64;
    const int grp = lane >> 2;
    const int tig = lane & 3;

    float acc[2][8][4] = {};
    float4 ra[2], rw[2];

    const int r0 = tid >> 2,        q0 = (tid & 3) * 4;
    const int r1 = (tid + 256) >> 2, q1 = q0;   // second half rows 64..127

    // prefetch k0 = 0
    ra[0] = *(const float4*)(A + (size_t)(bm + r0) * K + q0);
    ra[1] = *(const float4*)(A + (size_t)(bm + r1) * K + q1);
    rw[0] = *(const float4*)(W + (size_t)(bn + r0) * K + q0);
    rw[1] = *(const float4*)(W + (size_t)(bn + r1) * K + q1);

    for (int k0 = 0; k0 < K; k0 += 16) {
        cvt_store4(As + r0 * PAD + q0, ra[0]);
        cvt_store4(As + r1 * PAD + q1, ra[1]);
        cvt_store4(Ws + r0 * PAD + q0, rw[0]);
        cvt_store4(Ws + r1 * PAD + q1, rw[1]);
        __syncthreads();

        if (k0 + 16 < K) {
            int kn = k0 + 16;
            ra[0] = *(const float4*)(A + (size_t)(bm + r0) * K + kn + q0);
            ra[1] = *(const float4*)(A + (size_t)(bm + r1) * K + kn + q1);
            rw[0] = *(const float4*)(W + (size_t)(bn + r0) * K + kn + q0);
            rw[1] = *(const float4*)(W + (size_t)(bn + r1) * K + kn + q1);
        }

        #pragma unroll
        for (int ks = 0; ks < 2; ks++) {
            unsigned a[2][4], b[8][2];
            #pragma unroll
            for (int mi = 0; mi < 2; mi++) {
                const unsigned* p = As + (wm + mi * 16 + grp) * PAD + ks * 8 + tig;
                a[mi][0] = p[0];
                a[mi][1] = p[8 * PAD];
                a[mi][2] = p[4];
                a[mi][3] = p[8 * PAD + 4];
            }
            #pragma unroll
            for (int ni = 0; ni < 8; ni++) {
                const unsigned* p = Ws + (wn + ni * 8 + grp) * PAD + ks * 8 + tig;
                b[ni][0] = p[0];
                b[ni][1] = p[4];
            }
            #pragma unroll
            for (int mi = 0; mi < 2; mi++)
                #pragma unroll
                for (int ni = 0; ni < 8; ni++)
                    mma_tf32(acc[mi][ni], a[mi][0], a[mi][1], a[mi][2], a[mi][3],
                             b[ni][0], b[ni][1]);
        }
        __syncthreads();
    }

    #pragma unroll
    for (int mi = 0; mi < 2; mi++) {
        int row = bm + wm + mi * 16 + grp;
        #pragma unroll
        for (int ni = 0; ni < 8; ni++) {
            int col = bn + wn + ni * 8 + 2 * tig;
            float bv0 = bias[col], bv1 = bias[col + 1];
            float2 v0 = { (acc[mi][ni][0] + bv0) * alpha, (acc[mi][ni][1] + bv1) * alpha };
            float2 v1 = { (acc[mi][ni][2] + bv0) * alpha, (acc[mi][ni][3] + bv1) * alpha };
            *(float2*)(C + (size_t)row * N + col)       = v0;
            *(float2*)(C + (size_t)(row + 8) * N + col) = v1;
        }
    }
}

// ============================================================================
// logits (tf32 mma): g_w[b,h,t,s] = Q.K^T + attn_mask, -inf on padding
// block 128(t) x 128(s), K=D=64 in 4 x BK16 tiles, per (b,h) in z
// ============================================================================
__global__ __launch_bounds__(256)
void logits_mma(const float* __restrict__ attn_mask,
                const unsigned char* __restrict__ pad_mask)
{
    __shared__ unsigned Qs[128 * PAD];
    __shared__ unsigned Ks[128 * PAD];

    const int bh = blockIdx.z;
    const int b  = bh / HH;
    const int h  = bh % HH;
    const int t0 = blockIdx.y * 128;
    const int s0 = blockIdx.x * 128;

    const int tid  = threadIdx.x;
    const int wid  = tid >> 5;
    const int lane = tid & 31;
    const int wm = (wid >> 1) * 32;
    const int wn = (wid & 1) * 64;
    const int grp = lane >> 2;
    const int tig = lane & 3;

    const float* qb = g_q + (size_t)b * EE + h * DD;
    const float* kb = g_k + (size_t)b * EE + h * DD;

    float acc[2][8][4] = {};
    float4 ra[2], rw[2];

    const int r0 = tid >> 2,         q0 = (tid & 3) * 4;
    const int r1 = (tid + 256) >> 2;

    ra[0] = *(const float4*)(qb + (size_t)(t0 + r0) * BE + q0);
    ra[1] = *(const float4*)(qb + (size_t)(t0 + r1) * BE + q0);
    rw[0] = *(const float4*)(kb + (size_t)(s0 + r0) * BE + q0);
    rw[1] = *(const float4*)(kb + (size_t)(s0 + r1) * BE + q0);

    for (int k0 = 0; k0 < DD; k0 += 16) {
        cvt_store4(Qs + r0 * PAD + q0, ra[0]);
        cvt_store4(Qs + r1 * PAD + q0, ra[1]);
        cvt_store4(Ks + r0 * PAD + q0, rw[0]);
        cvt_store4(Ks + r1 * PAD + q0, rw[1]);
        __syncthreads();

        if (k0 + 16 < DD) {
            int kn = k0 + 16;
            ra[0] = *(const float4*)(qb + (size_t)(t0 + r0) * BE + kn + q0);
            ra[1] = *(const float4*)(qb + (size_t)(t0 + r1) * BE + kn + q0);
            rw[0] = *(const float4*)(kb + (size_t)(s0 + r0) * BE + kn + q0);
            rw[1] = *(const float4*)(kb + (size_t)(s0 + r1) * BE + kn + q0);
        }

        #pragma unroll
        for (int ks = 0; ks < 2; ks++) {
            unsigned a[2][4], bfr[8][2];
            #pragma unroll
            for (int mi = 0; mi < 2; mi++) {
                const unsigned* p = Qs + (wm + mi * 16 + grp) * PAD + ks * 8 + tig;
                a[mi][0] = p[0]; a[mi][1] = p[8 * PAD]; a[mi][2] = p[4]; a[mi][3] = p[8 * PAD + 4];
            }
            #pragma unroll
            for (int ni = 0; ni < 8; ni++) {
                const unsigned* p = Ks + (wn + ni * 8 + grp) * PAD + ks * 8 + tig;
                bfr[ni][0] = p[0]; bfr[ni][1] = p[4];
            }
            #pragma unroll
            for (int mi = 0; mi < 2; mi++)
                #pragma unroll
                for (int ni = 0; ni < 8; ni++)
                    mma_tf32(acc[mi][ni], a[mi][0], a[mi][1], a[mi][2], a[mi][3],
                             bfr[ni][0], bfr[ni][1]);
        }
        __syncthreads();
    }

    const float NEG = __int_as_float(0xff800000);
    float* out = g_w + (size_t)bh * TT * SS;

    #pragma unroll
    for (int mi = 0; mi < 2; mi++) {
        int t = t0 + wm + mi * 16 + grp;
        #pragma unroll
        for (int ni = 0; ni < 8; ni++) {
            int s = s0 + wn + ni * 8 + 2 * tig;
            bool p0 = pad_mask[b * SS + s];
            bool p1 = pad_mask[b * SS + s + 1];
            float2 v0, v1;
            v0.x = p0 ? NEG : acc[mi][ni][0] + attn_mask[(size_t)t * SS + s];
            v0.y = p1 ? NEG : acc[mi][ni][1] + attn_mask[(size_t)t * SS + s + 1];
            v1.x = p0 ? NEG : acc[mi][ni][2] + attn_mask[(size_t)(t + 8) * SS + s];
            v1.y = p1 ? NEG : acc[mi][ni][3] + attn_mask[(size_t)(t + 8) * SS + s + 1];
            *(float2*)(out + (size_t)t * SS + s)       = v0;
            *(float2*)(out + (size_t)(t + 8) * SS + s) = v1;
        }
    }
}

// ============================================================================
// Fused softmax (in-place on g_w, per head) + head-max + BCE per (b,t)
// ============================================================================
__global__ __launch_bounds__(256)
void smax_arc_kernel(const int* __restrict__ target_rel)
{
    const int t = blockIdx.x;
    const int b = blockIdx.y;
    const int tid  = threadIdx.x;
    const int lane = tid & 31;
    const int wid  = tid >> 5;
    __shared__ float red[40];

    float hm0 = 0.f, hm1 = 0.f, hm2 = 0.f, hm3 = 0.f;

    for (int h = 0; h < HH; h++) {
        float* row = g_w + (((size_t)(b * HH + h)) * TT + t) * SS;
        float4 v = ((float4*)row)[tid];

        float m = fmaxf(fmaxf(v.x, v.y), fmaxf(v.z, v.w));
        #pragma unroll
        for (int o = 16; o > 0; o >>= 1) m = fmaxf(m, __shfl_xor_sync(~0u, m, o));
        if (lane == 0) red[wid] = m;
        __syncthreads();
        if (wid == 0) {
            float mm = red[lane & 7];
            #pragma unroll
            for (int o = 4; o > 0; o >>= 1) mm = fmaxf(mm, __shfl_xor_sync(~0u, mm, o));
            if (lane == 0) red[32] = mm;
        }
        __syncthreads();
        m = red[32];

        v.x = __expf(v.x - m); v.y = __expf(v.y - m);
        v.z = __expf(v.z - m); v.w = __expf(v.w - m);
        float s = v.x + v.y + v.z + v.w;
        #pragma unroll
        for (int o = 16; o > 0; o >>= 1) s += __shfl_xor_sync(~0u, s, o);
        if (lane == 0) red[wid + 8] = s;
        __syncthreads();
        if (wid == 0) {
            float ss = red[8 + (lane & 7)];
            #pragma unroll
            for (int o = 4; o > 0; o >>= 1) ss += __shfl_xor_sync(~0u, ss, o);
            if (lane == 0) red[33] = ss;
        }
        __syncthreads();
        float inv = 1.f / red[33];

        v.x *= inv; v.y *= inv; v.z *= inv; v.w *= inv;
        ((float4*)row)[tid] = v;
        hm0 = fmaxf(hm0, v.x); hm1 = fmaxf(hm1, v.y);
        hm2 = fmaxf(hm2, v.z); hm3 = fmaxf(hm3, v.w);
        __syncthreads();
    }

    // BCE: rel==0 -> 0; rel==1 -> -max(log(w),-100); rel==2 -> -max(log1p(-w),-100)
    int4 rel = ((const int4*)(target_rel + ((size_t)t * BB + b) * SS))[tid];
    float sum = 0.f;
    if (rel.x == 1) sum -= fmaxf(logf(hm0), -100.f); else if (rel.x == 2) sum -= fmaxf(log1pf(-hm0), -100.f);
    if (rel.y == 1) sum -= fmaxf(logf(hm1), -100.f); else if (rel.y == 2) sum -= fmaxf(log1pf(-hm1), -100.f);
    if (rel.z == 1) sum -= fmaxf(logf(hm2), -100.f); else if (rel.z == 2) sum -= fmaxf(log1pf(-hm2), -100.f);
    if (rel.w == 1) sum -= fmaxf(logf(hm3), -100.f); else if (rel.w == 2) sum -= fmaxf(log1pf(-hm3), -100.f);

    #pragma unroll
    for (int o = 16; o > 0; o >>= 1) sum += __shfl_xor_sync(~0u, sum, o);
    if (lane == 0) red[wid + 16] = sum;
    __syncthreads();
    if (wid == 0) {
        float ss = red[16 + (lane & 7)];
        #pragma unroll
        for (int o = 4; o > 0; o >>= 1) ss += __shfl_xor_sync(~0u, ss, o);
        if (lane == 0) g_partBT[b * TT + t] = ss;
    }
}

__global__ void finalize_kernel(const float* __restrict__ strategy_id,
                                float* __restrict__ out)
{
    __shared__ float red[256];
    int b = blockIdx.x;
    int tid = threadIdx.x;
    float s = 0.f;
    for (int i = tid; i < TT; i += 256) s += g_partBT[b * TT + i];
    red[tid] = s; __syncthreads();
    #pragma unroll
    for (int o = 128; o > 0; o >>= 1) {
        if (tid < o) red[tid] += red[tid + o];
        __syncthreads();
    }
    if (tid == 0) out[b] = red[0] * strategy_id[b];
}

// ============================================================================
// attn·V (tf32 mma): g_attn[t,b,h*64+d] = sum_s w[b,h,t,s] * v[s,b,h,d]
// block 128(t) x 64(d), K=S=1024 in BK16 tiles, per (b,h) in y
// warp tile 32x32 (8 warps, 4x2)
// ============================================================================
__global__ __launch_bounds__(256)
void attnv_mma()
{
    __shared__ unsigned Asm[128 * PAD];   // weights [t][k]
    __shared__ unsigned Vsm[16 * PADV];   // V tile [k(s)][n(d)]

    const int bh = blockIdx.y;
    const int b  = bh / HH;
    const int h  = bh % HH;
    const int t0 = blockIdx.x * 128;

    const int tid  = threadIdx.x;
    const int wid  = tid >> 5;
    const int lane = tid & 31;
    const int wm = (wid >> 1) * 32;
    const int wn = (wid & 1) * 32;
    const int grp = lane >> 2;
    const int tig = lane & 3;

    const float* wb = g_w + ((size_t)bh * TT + t0) * SS;
    const float* vb = g_v + (size_t)b * EE + h * DD;

    float acc[2][4][4] = {};
    float4 ra[2], rv;

    const int r0 = tid >> 2,         q0 = (tid & 3) * 4;
    const int r1 = (tid + 256) >> 2;
    const int vr = tid >> 4,         vq = (tid & 15) * 4;   // V tile: 16 rows x 64

    ra[0] = *(const float4*)(wb + (size_t)r0 * SS + q0);
    ra[1] = *(const float4*)(wb + (size_t)r1 * SS + q0);
    rv    = *(const float4*)(vb + (size_t)vr * BE + vq);

    for (int k0 = 0; k0 < SS; k0 += 16) {
        cvt_store4(Asm + r0 * PAD + q0, ra[0]);
        cvt_store4(Asm + r1 * PAD + q0, ra[1]);
        cvt_store4(Vsm + vr * PADV + vq, rv);
        __syncthreads();

        if (k0 + 16 < SS) {
            int kn = k0 + 16;
            ra[0] = *(const float4*)(wb + (size_t)r0 * SS + kn + q0);
            ra[1] = *(const float4*)(wb + (size_t)r1 * SS + kn + q0);
            rv    = *(const float4*)(vb + (size_t)(kn + vr) * BE + vq);
        }

        #pragma unroll
        for (int ks = 0; ks < 2; ks++) {
            unsigned a[2][4], bfr[4][2];
            #pragma unroll
            for (int mi = 0; mi < 2; mi++) {
                const unsigned* p = Asm + (wm + mi * 16 + grp) * PAD + ks * 8 + tig;
                a[mi][0] = p[0]; a[mi][1] = p[8 * PAD]; a[mi][2] = p[4]; a[mi][3] = p[8 * PAD + 4];
            }
            #pragma unroll
            for (int ni = 0; ni < 4; ni++) {
                // B element (k,n) from [k][n] layout
                const unsigned* p = Vsm + (ks * 8 + tig) * PADV + wn + ni * 8 + grp;
                bfr[ni][0] = p[0];
                bfr[ni][1] = p[4 * PADV];
            }
            #pragma unroll
            for (int mi = 0; mi < 2; mi++)
                #pragma unroll
                for (int ni = 0; ni < 4; ni++)
                    mma_tf32(acc[mi][ni], a[mi][0], a[mi][1], a[mi][2], a[mi][3],
                             bfr[ni][0], bfr[ni][1]);
        }
        __syncthreads();
    }

    float* ob = g_attn + (size_t)b * EE + h * DD;
    #pragma unroll
    for (int mi = 0; mi < 2; mi++) {
        int t = t0 + wm + mi * 16 + grp;
        #pragma unroll
        for (int ni = 0; ni < 4; ni++) {
            int d = wn + ni * 8 + 2 * tig;
            *(float2*)(ob + (size_t)t * BE + d)       = make_float2(acc[mi][ni][0], acc[mi][ni][1]);
            *(float2*)(ob + (size_t)(t + 8) * BE + d) = make_float2(acc[mi][ni][2], acc[mi][ni][3]);
        }
    }
}

// ============================================================================
// launch
// ============================================================================
extern "C" void kernel_launch(void* const* d_in, const int* in_sizes, int n_in,
                              void* d_out, int out_size)
{
    const float* outs        = (const float*)d_in[2];
    const float* graph_state = (const float*)d_in[3];
    const unsigned char* pad = (const unsigned char*)d_in[4];
    const float* attn_mask   = (const float*)d_in[5];
    const float* strategy_id = (const float*)d_in[6];
    const int*   target_rel  = (const int*)d_in[7];
    const float* Win         = (const float*)d_in[8];
    const float* b_in        = (const float*)d_in[9];
    const float* Wout        = (const float*)d_in[10];
    const float* b_out       = (const float*)d_in[11];

    float* out_f    = (float*)d_out;
    float* out_loss = out_f;
    float* out_outs = out_f + 8;
    float* out_x    = out_f + 8 + (size_t)TT * BB * EE;

    float *qp, *kp, *vp, *ap;
    cudaGetSymbolAddress((void**)&qp, g_q);
    cudaGetSymbolAddress((void**)&kp, g_k);
    cudaGetSymbolAddress((void**)&vp, g_v);
    cudaGetSymbolAddress((void**)&ap, g_attn);

    dim3 gproj(EE / 128, MM / 128);   // (6, 64)

    sgemm_nt_mma<<<gproj, 256>>>(outs,        Win,               b_in,           qp, MM, EE, EE, 0.125f);
    sgemm_nt_mma<<<gproj, 256>>>(graph_state, Win + EE * EE,     b_in + EE,      kp, MM, EE, EE, 1.0f);
    sgemm_nt_mma<<<gproj, 256>>>(graph_state, Win + 2 * EE * EE, b_in + 2 * EE,  vp, MM, EE, EE, 1.0f);

    dim3 glog(SS / 128, TT / 128, BB * HH);   // (8,8,96)
    logits_mma<<<glog, 256>>>(attn_mask, pad);

    dim3 gsm(TT, BB);
    smax_arc_kernel<<<gsm, 256>>>(target_rel);
    finalize_kernel<<<BB, 256>>>(strategy_id, out_loss);

    dim3 gav(TT / 128, BB * HH);
    attnv_mma<<<gav, 256>>>();

    sgemm_nt_mma<<<gproj, 256>>>(ap, Wout, b_out, out_x, MM, EE, EE, 1.0f);

    cudaMemcpyAsync(out_outs, outs, (size_t)TT * BB * EE * sizeof(float),
                    cudaMemcpyDeviceToDevice);
}

// round 14
// speedup vs baseline: 1.0067x; 1.0001x over previous
#include <cuda_runtime.h>
#include <math.h>

#define TT 1024
#define SS 1024
#define BB 8
#define EE 768
#define HH 12
#define DD 64
#define MM (TT*BB)
#define BE (BB*EE)

#define PAD 20          // smem row stride (floats) for 16-wide k tiles -> conflict-free frags
#define PADV 68         // smem row stride for V tiles [16][64]

// ---------------- scratch ----------------
static __device__ float g_q[(size_t)TT * BB * EE];
static __device__ float g_k[(size_t)SS * BB * EE];
static __device__ float g_v[(size_t)SS * BB * EE];
static __device__ float g_w[(size_t)BB * HH * TT * SS];   // logits -> softmax weights
static __device__ float g_attn[(size_t)TT * BB * EE];
static __device__ float g_partBT[BB * TT];                // per (b,t) bce partials

// ---------------- helpers ----------------
__device__ __forceinline__ unsigned f2tf32(float f) {
    unsigned u;
    asm("cvt.rna.tf32.f32 %0, %1;" : "=r"(u) : "f"(f));
    return u;
}

__device__ __forceinline__ void mma_tf32(float c[4],
                                         unsigned a0, unsigned a1, unsigned a2, unsigned a3,
                                         unsigned b0, unsigned b1) {
    asm volatile("mma.sync.aligned.m16n8k8.row.col.f32.tf32.tf32.f32 "
                 "{%0,%1,%2,%3}, {%4,%5,%6,%7}, {%8,%9}, {%0,%1,%2,%3};"
                 : "+f"(c[0]), "+f"(c[1]), "+f"(c[2]), "+f"(c[3])
                 : "r"(a0), "r"(a1), "r"(a2), "r"(a3), "r"(b0), "r"(b1));
}

__device__ __forceinline__ void cvt_store4(unsigned* p, float4 v) {
    uint4 u;
    u.x = f2tf32(v.x); u.y = f2tf32(v.y); u.z = f2tf32(v.z); u.w = f2tf32(v.w);
    *(uint4*)p = u;
}

// ============================================================================
// SGEMM (tf32 mma): C[M,N] = (A[M,K] @ W[N,K]^T + bias) * alpha
// block tile 128x128, BK=16, 8 warps (4x2), warp tile 32x64
// ============================================================================
__global__ __launch_bounds__(256)
void sgemm_nt_mma(const float* __restrict__ A, const float* __restrict__ W,
                  const float* __restrict__ bias, float* __restrict__ C,
                  int M, int N, int K, float alpha)
{
    __shared__ unsigned As[128 * PAD];
    __shared__ unsigned Ws[128 * PAD];

    const int bm = blockIdx.y * 128;
    const int bn = blockIdx.x * 128;
    const int tid  = threadIdx.x;
    const int wid  = tid >> 5;
    const int lane = tid & 31;
    const int wm = (wid >> 1) * 32;
    const int wn = (wid & 1) * 64;
    const int grp = lane >> 2;
    const int tig = lane & 3;

    float acc[2][8][4] = {};
    float4 ra[2], rw[2];

    const int r0 = tid >> 2,        q0 = (tid & 3) * 4;
    const int r1 = (tid + 256) >> 2, q1 = q0;   // second half rows 64..127

    // prefetch k0 = 0
    ra[0] = *(const float4*)(A + (size_t)(bm + r0) * K + q0);
    ra[1] = *(const float4*)(A + (size_t)(bm + r1) * K + q1);
    rw[0] = *(const float4*)(W + (size_t)(bn + r0) * K + q0);
    rw[1] = *(const float4*)(W + (size_t)(bn + r1) * K + q1);

    for (int k0 = 0; k0 < K; k0 += 16) {
        cvt_store4(As + r0 * PAD + q0, ra[0]);
        cvt_store4(As + r1 * PAD + q1, ra[1]);
        cvt_store4(Ws + r0 * PAD + q0, rw[0]);
        cvt_store4(Ws + r1 * PAD + q1, rw[1]);
        __syncthreads();

        if (k0 + 16 < K) {
            int kn = k0 + 16;
            ra[0] = *(const float4*)(A + (size_t)(bm + r0) * K + kn + q0);
            ra[1] = *(const float4*)(A + (size_t)(bm + r1) * K + kn + q1);
            rw[0] = *(const float4*)(W + (size_t)(bn + r0) * K + kn + q0);
            rw[1] = *(const float4*)(W + (size_t)(bn + r1) * K + kn + q1);
        }

        #pragma unroll
        for (int ks = 0; ks < 2; ks++) {
            unsigned a[2][4], b[8][2];
            #pragma unroll
            for (int mi = 0; mi < 2; mi++) {
                const unsigned* p = As + (wm + mi * 16 + grp) * PAD + ks * 8 + tig;
                a[mi][0] = p[0];
                a[mi][1] = p[8 * PAD];
                a[mi][2] = p[4];
                a[mi][3] = p[8 * PAD + 4];
            }
            #pragma unroll
            for (int ni = 0; ni < 8; ni++) {
                const unsigned* p = Ws + (wn + ni * 8 + grp) * PAD + ks * 8 + tig;
                b[ni][0] = p[0];
                b[ni][1] = p[4];
            }
            #pragma unroll
            for (int mi = 0; mi < 2; mi++)
                #pragma unroll
                for (int ni = 0; ni < 8; ni++)
                    mma_tf32(acc[mi][ni], a[mi][0], a[mi][1], a[mi][2], a[mi][3],
                             b[ni][0], b[ni][1]);
        }
        __syncthreads();
    }

    #pragma unroll
    for (int mi = 0; mi < 2; mi++) {
        int row = bm + wm + mi * 16 + grp;
        #pragma unroll
        for (int ni = 0; ni < 8; ni++) {
            int col = bn + wn + ni * 8 + 2 * tig;
            float bv0 = bias[col], bv1 = bias[col + 1];
            float2 v0 = { (acc[mi][ni][0] + bv0) * alpha, (acc[mi][ni][1] + bv1) * alpha };
            float2 v1 = { (acc[mi][ni][2] + bv0) * alpha, (acc[mi][ni][3] + bv1) * alpha };
            *(float2*)(C + (size_t)row * N + col)       = v0;
            *(float2*)(C + (size_t)(row + 8) * N + col) = v1;
        }
    }
}

// ============================================================================
// logits (tf32 mma): g_w[b,h,t,s] = Q.K^T + attn_mask, -inf on padding
// block 128(t) x 128(s), K=D=64 in 4 x BK16 tiles, per (b,h) in z
// ============================================================================
__global__ __launch_bounds__(256)
void logits_mma(const float* __restrict__ attn_mask,
                const unsigned char* __restrict__ pad_mask)
{
    __shared__ unsigned Qs[128 * PAD];
    __shared__ unsigned Ks[128 * PAD];

    const int bh = blockIdx.z;
    const int b  = bh / HH;
    const int h  = bh % HH;
    const int t0 = blockIdx.y * 128;
    const int s0 = blockIdx.x * 128;

    const int tid  = threadIdx.x;
    const int wid  = tid >> 5;
    const int lane = tid & 31;
    const int wm = (wid >> 1) * 32;
    const int wn = (wid & 1) * 64;
    const int grp = lane >> 2;
    const int tig = lane & 3;

    const float* qb = g_q + (size_t)b * EE + h * DD;
    const float* kb = g_k + (size_t)b * EE + h * DD;

    float acc[2][8][4] = {};
    float4 ra[2], rw[2];

    const int r0 = tid >> 2,         q0 = (tid & 3) * 4;
    const int r1 = (tid + 256) >> 2;

    ra[0] = *(const float4*)(qb + (size_t)(t0 + r0) * BE + q0);
    ra[1] = *(const float4*)(qb + (size_t)(t0 + r1) * BE + q0);
    rw[0] = *(const float4*)(kb + (size_t)(s0 + r0) * BE + q0);
    rw[1] = *(const float4*)(kb + (size_t)(s0 + r1) * BE + q0);

    for (int k0 = 0; k0 < DD; k0 += 16) {
        cvt_store4(Qs + r0 * PAD + q0, ra[0]);
        cvt_store4(Qs + r1 * PAD + q0, ra[1]);
        cvt_store4(Ks + r0 * PAD + q0, rw[0]);
        cvt_store4(Ks + r1 * PAD + q0, rw[1]);
        __syncthreads();

        if (k0 + 16 < DD) {
            int kn = k0 + 16;
            ra[0] = *(const float4*)(qb + (size_t)(t0 + r0) * BE + kn + q0);
            ra[1] = *(const float4*)(qb + (size_t)(t0 + r1) * BE + kn + q0);
            rw[0] = *(const float4*)(kb + (size_t)(s0 + r0) * BE + kn + q0);
            rw[1] = *(const float4*)(kb + (size_t)(s0 + r1) * BE + kn + q0);
        }

        #pragma unroll
        for (int ks = 0; ks < 2; ks++) {
            unsigned a[2][4], bfr[8][2];
            #pragma unroll
            for (int mi = 0; mi < 2; mi++) {
                const unsigned* p = Qs + (wm + mi * 16 + grp) * PAD + ks * 8 + tig;
                a[mi][0] = p[0]; a[mi][1] = p[8 * PAD]; a[mi][2] = p[4]; a[mi][3] = p[8 * PAD + 4];
            }
            #pragma unroll
            for (int ni = 0; ni < 8; ni++) {
                const unsigned* p = Ks + (wn + ni * 8 + grp) * PAD + ks * 8 + tig;
                bfr[ni][0] = p[0]; bfr[ni][1] = p[4];
            }
            #pragma unroll
            for (int mi = 0; mi < 2; mi++)
                #pragma unroll
                for (int ni = 0; ni < 8; ni++)
                    mma_tf32(acc[mi][ni], a[mi][0], a[mi][1], a[mi][2], a[mi][3],
                             bfr[ni][0], bfr[ni][1]);
        }
        __syncthreads();
    }

    const float NEG = __int_as_float(0xff800000);
    float* out = g_w + (size_t)bh * TT * SS;

    #pragma unroll
    for (int mi = 0; mi < 2; mi++) {
        int t = t0 + wm + mi * 16 + grp;
        #pragma unroll
        for (int ni = 0; ni < 8; ni++) {
            int s = s0 + wn + ni * 8 + 2 * tig;
            bool p0 = pad_mask[b * SS + s];
            bool p1 = pad_mask[b * SS + s + 1];
            float2 v0, v1;
            v0.x = p0 ? NEG : acc[mi][ni][0] + attn_mask[(size_t)t * SS + s];
            v0.y = p1 ? NEG : acc[mi][ni][1] + attn_mask[(size_t)t * SS + s + 1];
            v1.x = p0 ? NEG : acc[mi][ni][2] + attn_mask[(size_t)(t + 8) * SS + s];
            v1.y = p1 ? NEG : acc[mi][ni][3] + attn_mask[(size_t)(t + 8) * SS + s + 1];
            *(float2*)(out + (size_t)t * SS + s)       = v0;
            *(float2*)(out + (size_t)(t + 8) * SS + s) = v1;
        }
    }
}

// ============================================================================
// Fused softmax (in-place on g_w, per head) + head-max + BCE per (b,t)
// ============================================================================
__global__ __launch_bounds__(256)
void smax_arc_kernel(const int* __restrict__ target_rel)
{
    const int t = blockIdx.x;
    const int b = blockIdx.y;
    const int tid  = threadIdx.x;
    const int lane = tid & 31;
    const int wid  = tid >> 5;
    __shared__ float red[40];

    float hm0 = 0.f, hm1 = 0.f, hm2 = 0.f, hm3 = 0.f;

    for (int h = 0; h < HH; h++) {
        float* row = g_w + (((size_t)(b * HH + h)) * TT + t) * SS;
        float4 v = ((float4*)row)[tid];

        float m = fmaxf(fmaxf(v.x, v.y), fmaxf(v.z, v.w));
        #pragma unroll
        for (int o = 16; o > 0; o >>= 1) m = fmaxf(m, __shfl_xor_sync(~0u, m, o));
        if (lane == 0) red[wid] = m;
        __syncthreads();
        if (wid == 0) {
            float mm = red[lane & 7];
            #pragma unroll
            for (int o = 4; o > 0; o >>= 1) mm = fmaxf(mm, __shfl_xor_sync(~0u, mm, o));
            if (lane == 0) red[32] = mm;
        }
        __syncthreads();
        m = red[32];

        v.x = __expf(v.x - m); v.y = __expf(v.y - m);
        v.z = __expf(v.z - m); v.w = __expf(v.w - m);
        float s = v.x + v.y + v.z + v.w;
        #pragma unroll
        for (int o = 16; o > 0; o >>= 1) s += __shfl_xor_sync(~0u, s, o);
        if (lane == 0) red[wid + 8] = s;
        __syncthreads();
        if (wid == 0) {
            float ss = red[8 + (lane & 7)];
            #pragma unroll
            for (int o = 4; o > 0; o >>= 1) ss += __shfl_xor_sync(~0u, ss, o);
            if (lane == 0) red[33] = ss;
        }
        __syncthreads();
        float inv = 1.f / red[33];

        v.x *= inv; v.y *= inv; v.z *= inv; v.w *= inv;
        ((float4*)row)[tid] = v;
        hm0 = fmaxf(hm0, v.x); hm1 = fmaxf(hm1, v.y);
        hm2 = fmaxf(hm2, v.z); hm3 = fmaxf(hm3, v.w);
        __syncthreads();
    }

    // BCE: rel==0 -> 0; rel==1 -> -max(log(w),-100); rel==2 -> -max(log1p(-w),-100)
    int4 rel = ((const int4*)(target_rel + ((size_t)t * BB + b) * SS))[tid];
    float sum = 0.f;
    if (rel.x == 1) sum -= fmaxf(logf(hm0), -100.f); else if (rel.x == 2) sum -= fmaxf(log1pf(-hm0), -100.f);
    if (rel.y == 1) sum -= fmaxf(logf(hm1), -100.f); else if (rel.y == 2) sum -= fmaxf(log1pf(-hm1), -100.f);
    if (rel.z == 1) sum -= fmaxf(logf(hm2), -100.f); else if (rel.z == 2) sum -= fmaxf(log1pf(-hm2), -100.f);
    if (rel.w == 1) sum -= fmaxf(logf(hm3), -100.f); else if (rel.w == 2) sum -= fmaxf(log1pf(-hm3), -100.f);

    #pragma unroll
    for (int o = 16; o > 0; o >>= 1) sum += __shfl_xor_sync(~0u, sum, o);
    if (lane == 0) red[wid + 16] = sum;
    __syncthreads();
    if (wid == 0) {
        float ss = red[16 + (lane & 7)];
        #pragma unroll
        for (int o = 4; o > 0; o >>= 1) ss += __shfl_xor_sync(~0u, ss, o);
        if (lane == 0) g_partBT[b * TT + t] = ss;
    }
}

__global__ void finalize_kernel(const float* __restrict__ strategy_id,
                                float* __restrict__ out)
{
    __shared__ float red[256];
    int b = blockIdx.x;
    int tid = threadIdx.x;
    float s = 0.f;
    for (int i = tid; i < TT; i += 256) s += g_partBT[b * TT + i];
    red[tid] = s; __syncthreads();
    #pragma unroll
    for (int o = 128; o > 0; o >>= 1) {
        if (tid < o) red[tid] += red[tid + o];
        __syncthreads();
    }
    if (tid == 0) out[b] = red[0] * strategy_id[b];
}

// ============================================================================
// attn·V (tf32 mma): g_attn[t,b,h*64+d] = sum_s w[b,h,t,s] * v[s,b,h,d]
// block 128(t) x 64(d), K=S=1024 in BK16 tiles, per (b,h) in y
// warp tile 32x32 (8 warps, 4x2)
// ============================================================================
__global__ __launch_bounds__(256)
void attnv_mma()
{
    __shared__ unsigned Asm[128 * PAD];   // weights [t][k]
    __shared__ unsigned Vsm[16 * PADV];   // V tile [k(s)][n(d)]

    const int bh = blockIdx.y;
    const int b  = bh / HH;
    const int h  = bh % HH;
    const int t0 = blockIdx.x * 128;

    const int tid  = threadIdx.x;
    const int wid  = tid >> 5;
    const int lane = tid & 31;
    const int wm = (wid >> 1) * 32;
    const int wn = (wid & 1) * 32;
    const int grp = lane >> 2;
    const int tig = lane & 3;

    const float* wb = g_w + ((size_t)bh * TT + t0) * SS;
    const float* vb = g_v + (size_t)b * EE + h * DD;

    float acc[2][4][4] = {};
    float4 ra[2], rv;

    const int r0 = tid >> 2,         q0 = (tid & 3) * 4;
    const int r1 = (tid + 256) >> 2;
    const int vr = tid >> 4,         vq = (tid & 15) * 4;   // V tile: 16 rows x 64

    ra[0] = *(const float4*)(wb + (size_t)r0 * SS + q0);
    ra[1] = *(const float4*)(wb + (size_t)r1 * SS + q0);
    rv    = *(const float4*)(vb + (size_t)vr * BE + vq);

    for (int k0 = 0; k0 < SS; k0 += 16) {
        cvt_store4(Asm + r0 * PAD + q0, ra[0]);
        cvt_store4(Asm + r1 * PAD + q0, ra[1]);
        cvt_store4(Vsm + vr * PADV + vq, rv);
        __syncthreads();

        if (k0 + 16 < SS) {
            int kn = k0 + 16;
            ra[0] = *(const float4*)(wb + (size_t)r0 * SS + kn + q0);
            ra[1] = *(const float4*)(wb + (size_t)r1 * SS + kn + q0);
            rv    = *(const float4*)(vb + (size_t)(kn + vr) * BE + vq);
        }

        #pragma unroll
        for (int ks = 0; ks < 2; ks++) {
            unsigned a[2][4], bfr[4][2];
            #pragma unroll
            for (int mi = 0; mi < 2; mi++) {
                const unsigned* p = Asm + (wm + mi * 16 + grp) * PAD + ks * 8 + tig;
                a[mi][0] = p[0]; a[mi][1] = p[8 * PAD]; a[mi][2] = p[4]; a[mi][3] = p[8 * PAD + 4];
            }
            #pragma unroll
            for (int ni = 0; ni < 4; ni++) {
                // B element (k,n) from [k][n] layout
                const unsigned* p = Vsm + (ks * 8 + tig) * PADV + wn + ni * 8 + grp;
                bfr[ni][0] = p[0];
                bfr[ni][1] = p[4 * PADV];
            }
            #pragma unroll
            for (int mi = 0; mi < 2; mi++)
                #pragma unroll
                for (int ni = 0; ni < 4; ni++)
                    mma_tf32(acc[mi][ni], a[mi][0], a[mi][1], a[mi][2], a[mi][3],
                             bfr[ni][0], bfr[ni][1]);
        }
        __syncthreads();
    }

    float* ob = g_attn + (size_t)b * EE + h * DD;
    #pragma unroll
    for (int mi = 0; mi < 2; mi++) {
        int t = t0 + wm + mi * 16 + grp;
        #pragma unroll
        for (int ni = 0; ni < 4; ni++) {
            int d = wn + ni * 8 + 2 * tig;
            *(float2*)(ob + (size_t)t * BE + d)       = make_float2(acc[mi][ni][0], acc[mi][ni][1]);
            *(float2*)(ob + (size_t)(t + 8) * BE + d) = make_float2(acc[mi][ni][2], acc[mi][ni][3]);
        }
    }
}

// ============================================================================
// launch
// ============================================================================
extern "C" void kernel_launch(void* const* d_in, const int* in_sizes, int n_in,
                              void* d_out, int out_size)
{
    const float* outs        = (const float*)d_in[2];
    const float* graph_state = (const float*)d_in[3];
    const unsigned char* pad = (const unsigned char*)d_in[4];
    const float* attn_mask   = (const float*)d_in[5];
    const float* strategy_id = (const float*)d_in[6];
    const int*   target_rel  = (const int*)d_in[7];
    const float* Win         = (const float*)d_in[8];
    const float* b_in        = (const float*)d_in[9];
    const float* Wout        = (const float*)d_in[10];
    const float* b_out       = (const float*)d_in[11];

    float* out_f    = (float*)d_out;
    float* out_loss = out_f;
    float* out_outs = out_f + 8;
    float* out_x    = out_f + 8 + (size_t)TT * BB * EE;

    float *qp, *kp, *vp, *ap;
    cudaGetSymbolAddress((void**)&qp, g_q);
    cudaGetSymbolAddress((void**)&kp, g_k);
    cudaGetSymbolAddress((void**)&vp, g_v);
    cudaGetSymbolAddress((void**)&ap, g_attn);

    dim3 gproj(EE / 128, MM / 128);   // (6, 64)

    sgemm_nt_mma<<<gproj, 256>>>(outs,        Win,               b_in,           qp, MM, EE, EE, 0.125f);
    sgemm_nt_mma<<<gproj, 256>>>(graph_state, Win + EE * EE,     b_in + EE,      kp, MM, EE, EE, 1.0f);
    sgemm_nt_mma<<<gproj, 256>>>(graph_state, Win + 2 * EE * EE, b_in + 2 * EE,  vp, MM, EE, EE, 1.0f);

    dim3 glog(SS / 128, TT / 128, BB * HH);   // (8,8,96)
    logits_mma<<<glog, 256>>>(attn_mask, pad);

    dim3 gsm(TT, BB);
    smax_arc_kernel<<<gsm, 256>>>(target_rel);
    finalize_kernel<<<BB, 256>>>(strategy_id, out_loss);

    dim3 gav(TT / 128, BB * HH);
    attnv_mma<<<gav, 256>>>();

    sgemm_nt_mma<<<gproj, 256>>>(ap, Wout, b_out, out_x, MM, EE, EE, 1.0f);

    cudaMemcpyAsync(out_outs, outs, (size_t)TT * BB * EE * sizeof(float),
                    cudaMemcpyDeviceToDevice);
}